// round 5
// baseline (speedup 1.0000x reference)
#include <cuda_runtime.h>
#include <math.h>

// Problem constants (fixed shapes from reference setup_inputs)
#define NMAX 40000
#define EMAX 640000
#define HID  128
#define FIN  64
#define FOUT 64
#define STATS_BLOCKS 1024
#define SCAN_BLK 256

// ---------------- device scratch (allocation-free: static globals) ----------------
__device__ float g_A[NMAX * HID];      // x @ W1a.T   [N,128]
__device__ float g_B[NMAX * HID];      // x @ W1b.T   [N,128]
__device__ float g_h1[NMAX * HID];     // h1 rows 0..N  (A[src]+B[dst])
__device__ float g_agg1[NMAX * HID];   // edge-aggregated h1
__device__ float g_wz[NMAX * FOUT];    // W2l @ r_j for j<N
__device__ float g_wa2[NMAX * FOUT];   // edge-aggregated wz
__device__ int   g_cnt[NMAX];
__device__ int   g_fill[NMAX];
__device__ int   g_rowptr[NMAX + 1];
__device__ int   g_bsum[(NMAX + SCAN_BLK - 1) / SCAN_BLK + 1];
__device__ int   g_eid[EMAX];
__device__ int   g_csrc[EMAX];
__device__ float g_cnorm[EMAX];
__device__ float g_dis[NMAX];
__device__ float g_invdeg[NMAX];
__device__ float g_part[STATS_BLOCKS * 2 * HID];
__device__ float g_af[HID];
__device__ float g_cf[HID];
__device__ float g_W2l[FOUT * HID];    // Wl @ W2  [64,128]
__device__ float g_cvec[FOUT];         // Wl@b2 + bl

// ---------------- f32x2 helpers ----------------
__device__ __forceinline__ unsigned long long fma2(unsigned long long a,
                                                   unsigned long long b,
                                                   unsigned long long c) {
    unsigned long long d;
    asm("fma.rn.f32x2 %0, %1, %2, %3;" : "=l"(d) : "l"(a), "l"(b), "l"(c));
    return d;
}
__device__ __forceinline__ unsigned long long add2(unsigned long long a,
                                                   unsigned long long b) {
    unsigned long long d;
    asm("add.rn.f32x2 %0, %1, %2;" : "=l"(d) : "l"(a), "l"(b));
    return d;
}
__device__ __forceinline__ unsigned long long packf2(float lo, float hi) {
    return ((unsigned long long)__float_as_uint(hi) << 32) | __float_as_uint(lo);
}
__device__ __forceinline__ float f2lo(unsigned long long a) {
    return __uint_as_float((unsigned int)a);
}
__device__ __forceinline__ float f2hi(unsigned long long a) {
    return __uint_as_float((unsigned int)(a >> 32));
}

// ---------------- kernels ----------------

__global__ void k_zero(int Ncur) {
    int t = blockIdx.x * blockDim.x + threadIdx.x;
    if (t < Ncur) { g_cnt[t] = 0; g_fill[t] = 0; }
}

__global__ void k_count(const int* __restrict__ dst, int Ecur) {
    int e = blockIdx.x * blockDim.x + threadIdx.x;
    if (e < Ecur) atomicAdd(&g_cnt[dst[e]], 1);
}

// scan pass 1: per-block exclusive scan + block totals; fused deg normalizers
__global__ void __launch_bounds__(SCAN_BLK) k_scan1(int Ncur) {
    __shared__ int sh[SCAN_BLK];
    int t = threadIdx.x;
    int idx = blockIdx.x * SCAN_BLK + t;
    int v = (idx < Ncur) ? g_cnt[idx] : 0;
    if (idx < Ncur) {
        float dg = (float)(v + 1);
        g_dis[idx]    = rsqrtf(dg);
        g_invdeg[idx] = 1.0f / dg;
    }
    sh[t] = v;
    __syncthreads();
#pragma unroll
    for (int off = 1; off < SCAN_BLK; off <<= 1) {
        int xv = (t >= off) ? sh[t - off] : 0;
        __syncthreads();
        sh[t] += xv;
        __syncthreads();
    }
    if (idx < Ncur) g_rowptr[idx] = sh[t] - v;
    if (t == SCAN_BLK - 1) g_bsum[blockIdx.x] = sh[t];
}

// scan pass 2: exclusive scan of block sums (nb <= SCAN_BLK)
__global__ void __launch_bounds__(SCAN_BLK) k_scan2(int nb) {
    __shared__ int sh[SCAN_BLK];
    int t = threadIdx.x;
    int v = (t < nb) ? g_bsum[t] : 0;
    sh[t] = v;
    __syncthreads();
#pragma unroll
    for (int off = 1; off < SCAN_BLK; off <<= 1) {
        int xv = (t >= off) ? sh[t - off] : 0;
        __syncthreads();
        sh[t] += xv;
        __syncthreads();
    }
    if (t < nb) g_bsum[t] = sh[t] - v;
}

// scan pass 3: apply block offsets; rowptr[N] = E
__global__ void k_scan3(int Ncur, int Ecur) {
    int idx = blockIdx.x * blockDim.x + threadIdx.x;
    if (idx < Ncur) g_rowptr[idx] += g_bsum[idx >> 8];
    if (idx == Ncur) g_rowptr[Ncur] = Ecur;
}

__global__ void k_fill(const int* __restrict__ dst, int Ecur) {
    int e = blockIdx.x * blockDim.x + threadIdx.x;
    if (e < Ecur) {
        int d = dst[e];
        int slot = g_rowptr[d] + atomicAdd(&g_fill[d], 1);
        g_eid[slot] = e;
    }
}

// sort each bucket by edge id (determinism), emit src + norm per slot.
// Buckets <= 64 sorted in a local (L1-resident) buffer.
__global__ void k_sort(const int* __restrict__ src, int Ncur) {
    int i = blockIdx.x * blockDim.x + threadIdx.x;
    if (i >= Ncur) return;
    int lo = g_rowptr[i], hi = g_rowptr[i + 1];
    int n = hi - lo;
    float di = g_dis[i];
    if (n <= 64) {
        int buf[64];
        for (int k = 0; k < n; k++) buf[k] = g_eid[lo + k];
        for (int a = 1; a < n; a++) {
            int key = buf[a];
            int b = a - 1;
            while (b >= 0 && buf[b] > key) { buf[b + 1] = buf[b]; b--; }
            buf[b + 1] = key;
        }
        for (int k = 0; k < n; k++) {
            int s = src[buf[k]];
            g_csrc[lo + k]  = s;
            g_cnorm[lo + k] = di * g_dis[s];
        }
    } else {
        for (int a = lo + 1; a < hi; a++) {
            int key = g_eid[a];
            int b = a - 1;
            while (b >= lo && g_eid[b] > key) { g_eid[b + 1] = g_eid[b]; b--; }
            g_eid[b + 1] = key;
        }
        for (int k = lo; k < hi; k++) {
            int s = src[g_eid[k]];
            g_csrc[k]  = s;
            g_cnorm[k] = di * g_dis[s];
        }
    }
}

// A = x @ W1[:, :64].T ; B = x @ W1[:, 64:].T   (16 nodes per block)
__global__ void __launch_bounds__(128) k_ab(const float* __restrict__ x,
                                            const float* __restrict__ W1, int Ncur) {
    __shared__ float xs[16][FIN];
    int j0 = blockIdx.x * 16;
    for (int idx = threadIdx.x; idx < 16 * FIN; idx += 128) {
        int j = idx >> 6, k = idx & 63;
        xs[j][k] = (j0 + j < Ncur) ? x[(j0 + j) * FIN + k] : 0.0f;
    }
    __syncthreads();
    int o = threadIdx.x;
    float accA[16], accB[16];
#pragma unroll
    for (int j = 0; j < 16; j++) { accA[j] = 0.f; accB[j] = 0.f; }
    const float* w = W1 + o * (2 * FIN);
    for (int k = 0; k < FIN; k++) {
        float wa = w[k], wb = w[FIN + k];
#pragma unroll
        for (int j = 0; j < 16; j++) {
            float xv = xs[j][k];
            accA[j] = fmaf(wa, xv, accA[j]);
            accB[j] = fmaf(wb, xv, accB[j]);
        }
    }
    for (int j = 0; j < 16; j++) {
        if (j0 + j < Ncur) {
            g_A[(j0 + j) * HID + o] = accA[j];
            g_B[(j0 + j) * HID + o] = accB[j];
        }
    }
}

// h1 rows 0..N-1: h1[j] = A[src[j]] + B[dst[j]]
__global__ void k_h1(const int* __restrict__ src, const int* __restrict__ dst, int Ncur) {
    int t = blockIdx.x * blockDim.x + threadIdx.x;
    if (t >= Ncur * HID) return;
    int j = t >> 7, f = t & 127;
    g_h1[t] = g_A[src[j] * HID + f] + g_B[dst[j] * HID + f];
}

// agg1[i] = sum over CSR bucket i of norm * h1[src]; indices staged in smem
__global__ void __launch_bounds__(128) k_agg1() {
    __shared__ int   ssrc[128];
    __shared__ float snorm[128];
    int i = blockIdx.x, f = threadIdx.x;
    int lo = g_rowptr[i], hi = g_rowptr[i + 1];
    float acc = 0.f;
    for (int base = lo; base < hi; base += 128) {
        int m = hi - base; if (m > 128) m = 128;
        if (f < m) { ssrc[f] = g_csrc[base + f]; snorm[f] = g_cnorm[base + f]; }
        __syncthreads();
        int k = 0;
        for (; k + 4 <= m; k += 4) {
            int s0 = ssrc[k], s1 = ssrc[k + 1], s2 = ssrc[k + 2], s3 = ssrc[k + 3];
            float n0 = snorm[k], n1 = snorm[k + 1], n2 = snorm[k + 2], n3 = snorm[k + 3];
            float v0 = g_h1[s0 * HID + f], v1 = g_h1[s1 * HID + f];
            float v2 = g_h1[s2 * HID + f], v3 = g_h1[s3 * HID + f];
            acc = fmaf(n0, v0, acc); acc = fmaf(n1, v1, acc);
            acc = fmaf(n2, v2, acc); acc = fmaf(n3, v3, acc);
        }
        for (; k < m; k++) acc = fmaf(snorm[k], g_h1[ssrc[k] * HID + f], acc);
        __syncthreads();
    }
    g_agg1[i * HID + f] = acc;
}

// BN stats: per-block partial sum/sumsq over pre-activation rows (fixed order)
__global__ void __launch_bounds__(128) k_bnstats(const int* __restrict__ src,
                                                 const int* __restrict__ dst,
                                                 const float* __restrict__ b1,
                                                 int Ncur, int Ecur) {
    int f = threadIdx.x;
    float bb = b1[f];
    float s_ = 0.f, q_ = 0.f;
    int stride = gridDim.x;
    int i = blockIdx.x;
    int sn = (i < Ecur) ? src[i] : 0, dn = (i < Ecur) ? dst[i] : 0;
    while (i < Ecur) {
        int inext = i + stride;
        float vA = g_A[sn * HID + f];
        float vB = g_B[dn * HID + f];
        float ag = 0.f, idg = 1.f;
        if (i < Ncur) { ag = g_agg1[i * HID + f]; idg = g_invdeg[i]; }
        if (inext < Ecur) { sn = src[inext]; dn = dst[inext]; }
        float v = idg * (vA + vB) + ag + bb;
        s_ += v;
        q_ = fmaf(v, v, q_);
        i = inext;
    }
    g_part[blockIdx.x * (2 * HID) + f]       = s_;
    g_part[blockIdx.x * (2 * HID) + HID + f] = q_;
}

// finalize BN: a = gamma*istd, c = beta - mu*a   (fixed-order reduce -> deterministic)
__global__ void k_bnred(const float* __restrict__ gamma, const float* __restrict__ beta, int Ecur) {
    int f = threadIdx.x;
    float s = 0.f, q = 0.f;
    for (int b = 0; b < STATS_BLOCKS; b++) {
        s += g_part[b * (2 * HID) + f];
        q += g_part[b * (2 * HID) + HID + f];
    }
    float invE = 1.0f / (float)Ecur;
    float mu  = s * invE;
    float var = q * invE - mu * mu;
    float istd = rsqrtf(var + 1e-5f);
    float a = gamma[f] * istd;
    g_af[f] = a;
    g_cf[f] = beta[f] - mu * a;
}

// W2l = Wl @ W2 ; cvec = Wl@b2 + bl
__global__ void k_w2l(const float* __restrict__ Wl, const float* __restrict__ W2,
                      const float* __restrict__ b2, const float* __restrict__ bl) {
    int t = blockIdx.x * blockDim.x + threadIdx.x;  // 8192 threads
    int o = t >> 7, f = t & 127;
    float acc = 0.f;
#pragma unroll
    for (int m = 0; m < 64; m++) acc = fmaf(Wl[o * 64 + m], W2[m * HID + f], acc);
    g_W2l[t] = acc;
    if (t < 64) {
        float cv = 0.f;
        for (int m = 0; m < 64; m++) cv = fmaf(Wl[t * 64 + m], b2[m], cv);
        g_cvec[t] = cv + bl[t];
    }
}

// wz[j] = W2l @ relu(bn(pre_j)) for j < N   (needed by aggregation 2)
__global__ void __launch_bounds__(128) k_z(const int* __restrict__ src,
                                           const int* __restrict__ dst,
                                           const float* __restrict__ b1, int Ncur) {
    int f = threadIdx.x;
    float bb = b1[f], af = g_af[f], cf = g_cf[f];
    int o = f & 63, h = f >> 6;
    float wreg[64];
#pragma unroll
    for (int k = 0; k < 64; k++) wreg[k] = g_W2l[o * HID + h * 64 + k];
    __shared__ __align__(16) float rsh[HID];
    __shared__ float ps[64];
    for (int j = blockIdx.x; j < Ncur; j += gridDim.x) {
        int s = src[j], d = dst[j];
        float v = g_A[s * HID + f] + g_B[d * HID + f];
        v = g_invdeg[j] * v + g_agg1[j * HID + f] + bb;
        rsh[f] = fmaxf(fmaf(af, v, cf), 0.f);
        __syncthreads();
        const float4* r4 = (const float4*)(rsh + h * 64);
        float a0 = 0.f, a1 = 0.f, a2 = 0.f, a3 = 0.f;
#pragma unroll
        for (int k = 0; k < 16; k++) {
            float4 rv = r4[k];
            a0 = fmaf(wreg[4 * k + 0], rv.x, a0);
            a1 = fmaf(wreg[4 * k + 1], rv.y, a1);
            a2 = fmaf(wreg[4 * k + 2], rv.z, a2);
            a3 = fmaf(wreg[4 * k + 3], rv.w, a3);
        }
        float part = (a0 + a1) + (a2 + a3);
        if (h) ps[o] = part;
        __syncthreads();
        if (!h) g_wz[j * FOUT + o] = part + ps[o];
        __syncthreads();
    }
}

// wa2[i] = sum over bucket i of norm * wz[src]; indices staged in smem
__global__ void __launch_bounds__(64) k_agg2() {
    __shared__ int   ssrc[64];
    __shared__ float snorm[64];
    int i = blockIdx.x, f = threadIdx.x;
    int lo = g_rowptr[i], hi = g_rowptr[i + 1];
    float acc = 0.f;
    for (int base = lo; base < hi; base += 64) {
        int m = hi - base; if (m > 64) m = 64;
        if (f < m) { ssrc[f] = g_csrc[base + f]; snorm[f] = g_cnorm[base + f]; }
        __syncthreads();
        int k = 0;
        for (; k + 4 <= m; k += 4) {
            int s0 = ssrc[k], s1 = ssrc[k + 1], s2 = ssrc[k + 2], s3 = ssrc[k + 3];
            float n0 = snorm[k], n1 = snorm[k + 1], n2 = snorm[k + 2], n3 = snorm[k + 3];
            float v0 = g_wz[s0 * FOUT + f], v1 = g_wz[s1 * FOUT + f];
            float v2 = g_wz[s2 * FOUT + f], v3 = g_wz[s3 * FOUT + f];
            acc = fmaf(n0, v0, acc); acc = fmaf(n1, v1, acc);
            acc = fmaf(n2, v2, acc); acc = fmaf(n3, v3, acc);
        }
        for (; k < m; k++) acc = fmaf(snorm[k], g_wz[ssrc[k] * FOUT + f], acc);
        __syncthreads();
    }
    g_wa2[i * FOUT + f] = acc;
}

// rows i < N: y = invdeg*wz + wa2 + cvec  (pure elementwise)
__global__ void k_small(const float* __restrict__ cutp, float* __restrict__ outp,
                        float* __restrict__ outr, int Ncur) {
    int t = blockIdx.x * blockDim.x + threadIdx.x;
    if (t >= Ncur * FOUT) return;
    int i = t >> 6, o = t & 63;
    float y = g_invdeg[i] * g_wz[t] + g_wa2[t] + g_cvec[o];
    float p = 1.0f / (1.0f + expf(-y));
    outp[t] = p;
    outr[t] = (p < *cutp) ? 0.0f : 1.0f;
}

// rows i in [N, E): tiled matvec, 2 rows/iter, f32x2 FMA, shuffle reduce.
// thread t: kc = t&7 (k-chunk of 16), og = t>>3 (4 outputs).
__global__ void __launch_bounds__(128) k_final(const int* __restrict__ src,
                                               const int* __restrict__ dst,
                                               const float* __restrict__ b1,
                                               const float* __restrict__ cutp,
                                               float* __restrict__ outp,
                                               float* __restrict__ outr,
                                               int Ncur, int Ecur) {
    const int t  = threadIdx.x;
    const int kc = t & 7;
    const int og = t >> 3;
    const int f  = t;  // feature handled in load phase

    float bb = b1[f], af = g_af[f], cf = g_cf[f];
    float cut = *cutp;
    float cv[4];
#pragma unroll
    for (int oo = 0; oo < 4; oo++) cv[oo] = g_cvec[og * 4 + oo];

    // W2l fragment: outputs og*4..og*4+3, k range kc*16..kc*16+15, packed (k,k+1)
    unsigned long long wp[4][8];
#pragma unroll
    for (int oo = 0; oo < 4; oo++) {
        const float2* wrow = (const float2*)(g_W2l + (og * 4 + oo) * HID + kc * 16);
#pragma unroll
        for (int j = 0; j < 8; j++) {
            float2 w = wrow[j];
            wp[oo][j] = packf2(w.x, w.y);
        }
    }

    __shared__ __align__(16) float rbuf[2][HID];

    int stride2 = gridDim.x * 2;
    for (int i = Ncur + blockIdx.x * 2; i < Ecur; i += stride2) {
        int i1 = i + 1;
        bool valid1 = (i1 < Ecur);
        int s0 = src[i], d0 = dst[i];
        int s1 = valid1 ? src[i1] : s0;
        int d1 = valid1 ? dst[i1] : d0;
        float vA0 = g_A[s0 * HID + f];
        float vB0 = g_B[d0 * HID + f];
        float vA1 = g_A[s1 * HID + f];
        float vB1 = g_B[d1 * HID + f];
        float r0 = fmaxf(fmaf(af, vA0 + vB0 + bb, cf), 0.f);
        float r1 = fmaxf(fmaf(af, vA1 + vB1 + bb, cf), 0.f);
        rbuf[0][f] = r0;
        rbuf[1][f] = r1;
        __syncthreads();

        unsigned long long acc[2][4];
#pragma unroll
        for (int rr = 0; rr < 2; rr++) {
            const ulonglong2* rp = (const ulonglong2*)(&rbuf[rr][kc * 16]);
#pragma unroll
            for (int oo = 0; oo < 4; oo++) acc[rr][oo] = 0ull;
#pragma unroll
            for (int j = 0; j < 4; j++) {
                ulonglong2 u = rp[j];  // covers k = 4j .. 4j+3 as two f32x2
#pragma unroll
                for (int oo = 0; oo < 4; oo++) {
                    acc[rr][oo] = fma2(wp[oo][2 * j],     u.x, acc[rr][oo]);
                    acc[rr][oo] = fma2(wp[oo][2 * j + 1], u.y, acc[rr][oo]);
                }
            }
        }
        // reduce over 8 k-chunks: kc lives in lane bits 0..2
#pragma unroll
        for (int rr = 0; rr < 2; rr++)
#pragma unroll
            for (int oo = 0; oo < 4; oo++) {
                unsigned long long a = acc[rr][oo];
                a = add2(a, __shfl_xor_sync(0xFFFFFFFFu, a, 1));
                a = add2(a, __shfl_xor_sync(0xFFFFFFFFu, a, 2));
                a = add2(a, __shfl_xor_sync(0xFFFFFFFFu, a, 4));
                acc[rr][oo] = a;
            }
        if (kc == 0) {
            float4 p4, q4;
            {
                float y0 = f2lo(acc[0][0]) + f2hi(acc[0][0]) + cv[0];
                float y1 = f2lo(acc[0][1]) + f2hi(acc[0][1]) + cv[1];
                float y2 = f2lo(acc[0][2]) + f2hi(acc[0][2]) + cv[2];
                float y3 = f2lo(acc[0][3]) + f2hi(acc[0][3]) + cv[3];
                p4.x = 1.0f / (1.0f + expf(-y0));
                p4.y = 1.0f / (1.0f + expf(-y1));
                p4.z = 1.0f / (1.0f + expf(-y2));
                p4.w = 1.0f / (1.0f + expf(-y3));
                q4.x = (p4.x < cut) ? 0.f : 1.f;
                q4.y = (p4.y < cut) ? 0.f : 1.f;
                q4.z = (p4.z < cut) ? 0.f : 1.f;
                q4.w = (p4.w < cut) ? 0.f : 1.f;
                *(float4*)(outp + (size_t)i * FOUT + og * 4) = p4;
                *(float4*)(outr + (size_t)i * FOUT + og * 4) = q4;
            }
            if (valid1) {
                float y0 = f2lo(acc[1][0]) + f2hi(acc[1][0]) + cv[0];
                float y1 = f2lo(acc[1][1]) + f2hi(acc[1][1]) + cv[1];
                float y2 = f2lo(acc[1][2]) + f2hi(acc[1][2]) + cv[2];
                float y3 = f2lo(acc[1][3]) + f2hi(acc[1][3]) + cv[3];
                p4.x = 1.0f / (1.0f + expf(-y0));
                p4.y = 1.0f / (1.0f + expf(-y1));
                p4.z = 1.0f / (1.0f + expf(-y2));
                p4.w = 1.0f / (1.0f + expf(-y3));
                q4.x = (p4.x < cut) ? 0.f : 1.f;
                q4.y = (p4.y < cut) ? 0.f : 1.f;
                q4.z = (p4.z < cut) ? 0.f : 1.f;
                q4.w = (p4.w < cut) ? 0.f : 1.f;
                *(float4*)(outp + (size_t)i1 * FOUT + og * 4) = p4;
                *(float4*)(outr + (size_t)i1 * FOUT + og * 4) = q4;
            }
        }
        __syncthreads();
    }
}

// ---------------- launch ----------------
extern "C" void kernel_launch(void* const* d_in, const int* in_sizes, int n_in,
                              void* d_out, int out_size) {
    const float* x     = (const float*)d_in[0];
    const int*   edge  = (const int*)d_in[1];
    const float* W1    = (const float*)d_in[2];
    const float* b1    = (const float*)d_in[3];
    const float* gamma = (const float*)d_in[4];
    const float* beta  = (const float*)d_in[5];
    const float* W2    = (const float*)d_in[6];
    const float* b2    = (const float*)d_in[7];
    const float* Wl    = (const float*)d_in[8];
    const float* bl    = (const float*)d_in[9];
    const float* cut   = (const float*)d_in[10];

    int Ncur = in_sizes[0] / FIN;
    int Ecur = in_sizes[1] / 2;
    if (Ncur > NMAX || Ecur > EMAX || Ncur <= 0 || Ecur <= 0) return;

    const int* src = edge;
    const int* dst = edge + Ecur;
    float* outp = (float*)d_out;
    float* outr = outp + (size_t)out_size / 2;

    int nb = (Ncur + SCAN_BLK - 1) / SCAN_BLK;

    k_zero <<<(Ncur + 255) / 256, 256>>>(Ncur);
    k_count<<<(Ecur + 255) / 256, 256>>>(dst, Ecur);
    k_scan1<<<nb, SCAN_BLK>>>(Ncur);
    k_scan2<<<1, SCAN_BLK>>>(nb);
    k_scan3<<<(Ncur + 256) / 256, 256>>>(Ncur, Ecur);
    k_fill <<<(Ecur + 255) / 256, 256>>>(dst, Ecur);
    k_sort <<<(Ncur + 127) / 128, 128>>>(src, Ncur);
    k_ab   <<<(Ncur + 15) / 16, 128>>>(x, W1, Ncur);
    k_h1   <<<(Ncur * HID + 255) / 256, 256>>>(src, dst, Ncur);
    k_agg1 <<<Ncur, 128>>>();
    k_bnstats<<<STATS_BLOCKS, 128>>>(src, dst, b1, Ncur, Ecur);
    k_bnred<<<1, 128>>>(gamma, beta, Ecur);
    k_w2l  <<<64, 128>>>(Wl, W2, b2, bl);
    {
        int g = Ncur < 2048 ? Ncur : 2048;
        k_z<<<g, 128>>>(src, dst, b1, Ncur);
    }
    k_agg2 <<<Ncur, 64>>>();
    k_small<<<(Ncur * FOUT + 255) / 256, 256>>>(cut, outp, outr, Ncur);
    {
        int rows = Ecur - Ncur;
        if (rows > 0) {
            int pairs = (rows + 1) / 2;
            int g = pairs < 2048 ? pairs : 2048;
            k_final<<<g, 128>>>(src, dst, b1, cut, outp, outr, Ncur, Ecur);
        }
    }
}

// round 6
// speedup vs baseline: 1.2477x; 1.2477x over previous
#include <cuda_runtime.h>
#include <math.h>

// Problem constants (fixed shapes from reference setup_inputs)
#define NMAX 40000
#define EMAX 640000
#define HID  128
#define FIN  64
#define FOUT 64
#define STATS_BLOCKS 1024
#define SCAN_BLK 256

// ---------------- device scratch (allocation-free: static globals) ----------------
__device__ float g_A[NMAX * HID];      // x @ W1a.T   [N,128]
__device__ float g_B[NMAX * HID];      // x @ W1b.T   [N,128]
__device__ float g_h1[NMAX * HID];     // h1 rows 0..N  (A[src]+B[dst])
__device__ float g_agg1[NMAX * HID];   // edge-aggregated h1
__device__ float g_wz[NMAX * FOUT];    // W2l @ r_j for j<N
__device__ float g_wa2[NMAX * FOUT];   // edge-aggregated wz
__device__ int   g_cnt[NMAX];
__device__ int   g_fill[NMAX];
__device__ int   g_rowptr[NMAX + 1];
__device__ int   g_bsum[(NMAX + SCAN_BLK - 1) / SCAN_BLK + 1];
__device__ int   g_eid[EMAX];
__device__ int   g_csrc[EMAX];
__device__ float g_cnorm[EMAX];
__device__ float g_dis[NMAX];
__device__ float g_invdeg[NMAX];
__device__ float g_part[STATS_BLOCKS * 2 * HID];
__device__ float g_af[HID];
__device__ float g_cf[HID];
__device__ float g_W2l[FOUT * HID];    // Wl @ W2  [64,128]
__device__ float g_cvec[FOUT];         // Wl@b2 + bl

// ---------------- kernels ----------------

__global__ void k_zero(int Ncur) {
    int t = blockIdx.x * blockDim.x + threadIdx.x;
    if (t < Ncur) { g_cnt[t] = 0; g_fill[t] = 0; }
}

__global__ void k_count(const int* __restrict__ dst, int Ecur) {
    int e = blockIdx.x * blockDim.x + threadIdx.x;
    if (e < Ecur) atomicAdd(&g_cnt[dst[e]], 1);
}

// scan pass 1: per-block exclusive scan + block totals; fused deg normalizers
__global__ void __launch_bounds__(SCAN_BLK) k_scan1(int Ncur) {
    __shared__ int sh[SCAN_BLK];
    int t = threadIdx.x;
    int idx = blockIdx.x * SCAN_BLK + t;
    int v = (idx < Ncur) ? g_cnt[idx] : 0;
    if (idx < Ncur) {
        float dg = (float)(v + 1);
        g_dis[idx]    = rsqrtf(dg);
        g_invdeg[idx] = 1.0f / dg;
    }
    sh[t] = v;
    __syncthreads();
#pragma unroll
    for (int off = 1; off < SCAN_BLK; off <<= 1) {
        int xv = (t >= off) ? sh[t - off] : 0;
        __syncthreads();
        sh[t] += xv;
        __syncthreads();
    }
    if (idx < Ncur) g_rowptr[idx] = sh[t] - v;
    if (t == SCAN_BLK - 1) g_bsum[blockIdx.x] = sh[t];
}

// scan pass 2: exclusive scan of block sums (nb <= SCAN_BLK)
__global__ void __launch_bounds__(SCAN_BLK) k_scan2(int nb) {
    __shared__ int sh[SCAN_BLK];
    int t = threadIdx.x;
    int v = (t < nb) ? g_bsum[t] : 0;
    sh[t] = v;
    __syncthreads();
#pragma unroll
    for (int off = 1; off < SCAN_BLK; off <<= 1) {
        int xv = (t >= off) ? sh[t - off] : 0;
        __syncthreads();
        sh[t] += xv;
        __syncthreads();
    }
    if (t < nb) g_bsum[t] = sh[t] - v;
}

// scan pass 3: apply block offsets; rowptr[N] = E
__global__ void k_scan3(int Ncur, int Ecur) {
    int idx = blockIdx.x * blockDim.x + threadIdx.x;
    if (idx < Ncur) g_rowptr[idx] += g_bsum[idx >> 8];
    if (idx == Ncur) g_rowptr[Ncur] = Ecur;
}

__global__ void k_fill(const int* __restrict__ dst, int Ecur) {
    int e = blockIdx.x * blockDim.x + threadIdx.x;
    if (e < Ecur) {
        int d = dst[e];
        int slot = g_rowptr[d] + atomicAdd(&g_fill[d], 1);
        g_eid[slot] = e;
    }
}

// sort each bucket by edge id (determinism), emit src + norm per slot.
// Buckets <= 64 sorted in a local (L1-resident) buffer.
__global__ void k_sort(const int* __restrict__ src, int Ncur) {
    int i = blockIdx.x * blockDim.x + threadIdx.x;
    if (i >= Ncur) return;
    int lo = g_rowptr[i], hi = g_rowptr[i + 1];
    int n = hi - lo;
    float di = g_dis[i];
    if (n <= 64) {
        int buf[64];
        for (int k = 0; k < n; k++) buf[k] = g_eid[lo + k];
        for (int a = 1; a < n; a++) {
            int key = buf[a];
            int b = a - 1;
            while (b >= 0 && buf[b] > key) { buf[b + 1] = buf[b]; b--; }
            buf[b + 1] = key;
        }
        for (int k = 0; k < n; k++) {
            int s = src[buf[k]];
            g_csrc[lo + k]  = s;
            g_cnorm[lo + k] = di * g_dis[s];
        }
    } else {
        for (int a = lo + 1; a < hi; a++) {
            int key = g_eid[a];
            int b = a - 1;
            while (b >= lo && g_eid[b] > key) { g_eid[b + 1] = g_eid[b]; b--; }
            g_eid[b + 1] = key;
        }
        for (int k = lo; k < hi; k++) {
            int s = src[g_eid[k]];
            g_csrc[k]  = s;
            g_cnorm[k] = di * g_dis[s];
        }
    }
}

// A = x @ W1[:, :64].T ; B = x @ W1[:, 64:].T   (16 nodes per block)
__global__ void __launch_bounds__(128) k_ab(const float* __restrict__ x,
                                            const float* __restrict__ W1, int Ncur) {
    __shared__ float xs[16][FIN];
    int j0 = blockIdx.x * 16;
    for (int idx = threadIdx.x; idx < 16 * FIN; idx += 128) {
        int j = idx >> 6, k = idx & 63;
        xs[j][k] = (j0 + j < Ncur) ? x[(j0 + j) * FIN + k] : 0.0f;
    }
    __syncthreads();
    int o = threadIdx.x;
    float accA[16], accB[16];
#pragma unroll
    for (int j = 0; j < 16; j++) { accA[j] = 0.f; accB[j] = 0.f; }
    const float* w = W1 + o * (2 * FIN);
    for (int k = 0; k < FIN; k++) {
        float wa = w[k], wb = w[FIN + k];
#pragma unroll
        for (int j = 0; j < 16; j++) {
            float xv = xs[j][k];
            accA[j] = fmaf(wa, xv, accA[j]);
            accB[j] = fmaf(wb, xv, accB[j]);
        }
    }
    for (int j = 0; j < 16; j++) {
        if (j0 + j < Ncur) {
            g_A[(j0 + j) * HID + o] = accA[j];
            g_B[(j0 + j) * HID + o] = accB[j];
        }
    }
}

// h1 rows 0..N-1: h1[j] = A[src[j]] + B[dst[j]]
__global__ void k_h1(const int* __restrict__ src, const int* __restrict__ dst, int Ncur) {
    int t = blockIdx.x * blockDim.x + threadIdx.x;
    if (t >= Ncur * HID) return;
    int j = t >> 7, f = t & 127;
    g_h1[t] = g_A[src[j] * HID + f] + g_B[dst[j] * HID + f];
}

// agg1[i] = sum over CSR bucket i of norm * h1[src]; indices staged in smem
__global__ void __launch_bounds__(128) k_agg1() {
    __shared__ int   ssrc[128];
    __shared__ float snorm[128];
    int i = blockIdx.x, f = threadIdx.x;
    int lo = g_rowptr[i], hi = g_rowptr[i + 1];
    float acc = 0.f;
    for (int base = lo; base < hi; base += 128) {
        int m = hi - base; if (m > 128) m = 128;
        if (f < m) { ssrc[f] = g_csrc[base + f]; snorm[f] = g_cnorm[base + f]; }
        __syncthreads();
        int k = 0;
        for (; k + 4 <= m; k += 4) {
            int s0 = ssrc[k], s1 = ssrc[k + 1], s2 = ssrc[k + 2], s3 = ssrc[k + 3];
            float n0 = snorm[k], n1 = snorm[k + 1], n2 = snorm[k + 2], n3 = snorm[k + 3];
            float v0 = g_h1[s0 * HID + f], v1 = g_h1[s1 * HID + f];
            float v2 = g_h1[s2 * HID + f], v3 = g_h1[s3 * HID + f];
            acc = fmaf(n0, v0, acc); acc = fmaf(n1, v1, acc);
            acc = fmaf(n2, v2, acc); acc = fmaf(n3, v3, acc);
        }
        for (; k < m; k++) acc = fmaf(snorm[k], g_h1[ssrc[k] * HID + f], acc);
        __syncthreads();
    }
    g_agg1[i * HID + f] = acc;
}

// BN stats: per-block partial sum/sumsq over pre-activation rows (fixed order)
__global__ void __launch_bounds__(128) k_bnstats(const int* __restrict__ src,
                                                 const int* __restrict__ dst,
                                                 const float* __restrict__ b1,
                                                 int Ncur, int Ecur) {
    int f = threadIdx.x;
    float bb = b1[f];
    float s_ = 0.f, q_ = 0.f;
    int stride = gridDim.x;
    int i = blockIdx.x;
    int sn = (i < Ecur) ? src[i] : 0, dn = (i < Ecur) ? dst[i] : 0;
    while (i < Ecur) {
        int inext = i + stride;
        float vA = g_A[sn * HID + f];
        float vB = g_B[dn * HID + f];
        float ag = 0.f, idg = 1.f;
        if (i < Ncur) { ag = g_agg1[i * HID + f]; idg = g_invdeg[i]; }
        if (inext < Ecur) { sn = src[inext]; dn = dst[inext]; }
        float v = idg * (vA + vB) + ag + bb;
        s_ += v;
        q_ = fmaf(v, v, q_);
        i = inext;
    }
    g_part[blockIdx.x * (2 * HID) + f]       = s_;
    g_part[blockIdx.x * (2 * HID) + HID + f] = q_;
}

// finalize BN: a = gamma*istd, c = beta - mu*a   (fixed-order reduce -> deterministic)
__global__ void k_bnred(const float* __restrict__ gamma, const float* __restrict__ beta, int Ecur) {
    int f = threadIdx.x;
    float s = 0.f, q = 0.f;
    for (int b = 0; b < STATS_BLOCKS; b++) {
        s += g_part[b * (2 * HID) + f];
        q += g_part[b * (2 * HID) + HID + f];
    }
    float invE = 1.0f / (float)Ecur;
    float mu  = s * invE;
    float var = q * invE - mu * mu;
    float istd = rsqrtf(var + 1e-5f);
    float a = gamma[f] * istd;
    g_af[f] = a;
    g_cf[f] = beta[f] - mu * a;
}

// W2l = Wl @ W2 ; cvec = Wl@b2 + bl
__global__ void k_w2l(const float* __restrict__ Wl, const float* __restrict__ W2,
                      const float* __restrict__ b2, const float* __restrict__ bl) {
    int t = blockIdx.x * blockDim.x + threadIdx.x;  // 8192 threads
    int o = t >> 7, f = t & 127;
    float acc = 0.f;
#pragma unroll
    for (int m = 0; m < 64; m++) acc = fmaf(Wl[o * 64 + m], W2[m * HID + f], acc);
    g_W2l[t] = acc;
    if (t < 64) {
        float cv = 0.f;
        for (int m = 0; m < 64; m++) cv = fmaf(Wl[t * 64 + m], b2[m], cv);
        g_cvec[t] = cv + bl[t];
    }
}

// wz[j] = W2l @ relu(bn(pre_j)) for j < N   (needed by aggregation 2)
// thread t: o = t>>1 (output), h = t&1 (k-half); partner-lane shuffle reduce.
__global__ void __launch_bounds__(128) k_z(const int* __restrict__ src,
                                           const int* __restrict__ dst,
                                           const float* __restrict__ b1, int Ncur) {
    int f = threadIdx.x;
    float bb = b1[f], af = g_af[f], cf = g_cf[f];
    int o = f >> 1, h = f & 1;
    float wreg[64];
#pragma unroll
    for (int k = 0; k < 64; k++) wreg[k] = g_W2l[o * HID + h * 64 + k];
    __shared__ __align__(16) float rsh[HID];
    for (int j = blockIdx.x; j < Ncur; j += gridDim.x) {
        int s = src[j], d = dst[j];
        float v = g_A[s * HID + f] + g_B[d * HID + f];
        v = g_invdeg[j] * v + g_agg1[j * HID + f] + bb;
        rsh[f] = fmaxf(fmaf(af, v, cf), 0.f);
        __syncthreads();
        const float4* r4 = (const float4*)(rsh + h * 64);
        float a0 = 0.f, a1 = 0.f, a2 = 0.f, a3 = 0.f;
#pragma unroll
        for (int k = 0; k < 16; k++) {
            float4 rv = r4[k];
            a0 = fmaf(wreg[4 * k + 0], rv.x, a0);
            a1 = fmaf(wreg[4 * k + 1], rv.y, a1);
            a2 = fmaf(wreg[4 * k + 2], rv.z, a2);
            a3 = fmaf(wreg[4 * k + 3], rv.w, a3);
        }
        float part = (a0 + a1) + (a2 + a3);
        part += __shfl_xor_sync(0xFFFFFFFFu, part, 1);
        if (!h) g_wz[j * FOUT + o] = part;
        __syncthreads();
    }
}

// wa2[i] = sum over bucket i of norm * wz[src]; indices staged in smem
__global__ void __launch_bounds__(64) k_agg2() {
    __shared__ int   ssrc[64];
    __shared__ float snorm[64];
    int i = blockIdx.x, f = threadIdx.x;
    int lo = g_rowptr[i], hi = g_rowptr[i + 1];
    float acc = 0.f;
    for (int base = lo; base < hi; base += 64) {
        int m = hi - base; if (m > 64) m = 64;
        if (f < m) { ssrc[f] = g_csrc[base + f]; snorm[f] = g_cnorm[base + f]; }
        __syncthreads();
        int k = 0;
        for (; k + 4 <= m; k += 4) {
            int s0 = ssrc[k], s1 = ssrc[k + 1], s2 = ssrc[k + 2], s3 = ssrc[k + 3];
            float n0 = snorm[k], n1 = snorm[k + 1], n2 = snorm[k + 2], n3 = snorm[k + 3];
            float v0 = g_wz[s0 * FOUT + f], v1 = g_wz[s1 * FOUT + f];
            float v2 = g_wz[s2 * FOUT + f], v3 = g_wz[s3 * FOUT + f];
            acc = fmaf(n0, v0, acc); acc = fmaf(n1, v1, acc);
            acc = fmaf(n2, v2, acc); acc = fmaf(n3, v3, acc);
        }
        for (; k < m; k++) acc = fmaf(snorm[k], g_wz[ssrc[k] * FOUT + f], acc);
        __syncthreads();
    }
    g_wa2[i * FOUT + f] = acc;
}

// rows i < N: y = invdeg*wz + wa2 + cvec  (pure elementwise)
__global__ void k_small(const float* __restrict__ cutp, float* __restrict__ outp,
                        float* __restrict__ outr, int Ncur) {
    int t = blockIdx.x * blockDim.x + threadIdx.x;
    if (t >= Ncur * FOUT) return;
    int i = t >> 6, o = t & 63;
    float y = g_invdeg[i] * g_wz[t] + g_wa2[t] + g_cvec[o];
    float p = 1.0f / (1.0f + expf(-y));
    outp[t] = p;
    outr[t] = (p < *cutp) ? 0.0f : 1.0f;
}

// rows i in [N, E): broadcast matvec, 2 rows/iter, partner-lane reduce.
// thread t: o = t>>1 (output 0..63), h = t&1 (k-half). Broadcast float4 LDS.
__global__ void __launch_bounds__(128) k_final(const int* __restrict__ src,
                                               const int* __restrict__ dst,
                                               const float* __restrict__ b1,
                                               const float* __restrict__ cutp,
                                               float* __restrict__ outp,
                                               float* __restrict__ outr,
                                               int Ncur, int Ecur) {
    int f = threadIdx.x;
    float bb = b1[f], af = g_af[f], cf = g_cf[f];
    int o = f >> 1, h = f & 1;
    float wreg[64];
#pragma unroll
    for (int k = 0; k < 64; k++) wreg[k] = g_W2l[o * HID + h * 64 + k];
    float cv  = g_cvec[o];
    float cut = *cutp;
    __shared__ __align__(16) float rsh[2][HID];

    int stride2 = gridDim.x * 2;
    for (int i = Ncur + blockIdx.x * 2; i < Ecur; i += stride2) {
        int i1 = i + 1;
        bool valid1 = (i1 < Ecur);
        int s0 = src[i], d0 = dst[i];
        int s1 = valid1 ? src[i1] : s0;
        int d1 = valid1 ? dst[i1] : d0;
        float vA0 = g_A[s0 * HID + f];
        float vB0 = g_B[d0 * HID + f];
        float vA1 = g_A[s1 * HID + f];
        float vB1 = g_B[d1 * HID + f];
        rsh[0][f] = fmaxf(fmaf(af, vA0 + vB0 + bb, cf), 0.f);
        rsh[1][f] = fmaxf(fmaf(af, vA1 + vB1 + bb, cf), 0.f);
        __syncthreads();

        const float4* r40 = (const float4*)(rsh[0] + h * 64);
        const float4* r41 = (const float4*)(rsh[1] + h * 64);
        float a0 = 0.f, a1 = 0.f, a2 = 0.f, a3 = 0.f;
        float c0 = 0.f, c1 = 0.f, c2 = 0.f, c3 = 0.f;
#pragma unroll
        for (int k = 0; k < 16; k++) {
            float4 u = r40[k];
            float4 w4 = r41[k];
            float w0 = wreg[4 * k + 0], w1 = wreg[4 * k + 1];
            float w2 = wreg[4 * k + 2], w3 = wreg[4 * k + 3];
            a0 = fmaf(w0, u.x, a0);  c0 = fmaf(w0, w4.x, c0);
            a1 = fmaf(w1, u.y, a1);  c1 = fmaf(w1, w4.y, c1);
            a2 = fmaf(w2, u.z, a2);  c2 = fmaf(w2, w4.z, c2);
            a3 = fmaf(w3, u.w, a3);  c3 = fmaf(w3, w4.w, c3);
        }
        float p0 = (a0 + a1) + (a2 + a3);
        float p1 = (c0 + c1) + (c2 + c3);
        p0 += __shfl_xor_sync(0xFFFFFFFFu, p0, 1);
        p1 += __shfl_xor_sync(0xFFFFFFFFu, p1, 1);
        if (!h) {
            float y0 = p0 + cv;
            float q0 = 1.0f / (1.0f + expf(-y0));
            size_t off0 = (size_t)i * FOUT + o;
            outp[off0] = q0;
            outr[off0] = (q0 < cut) ? 0.0f : 1.0f;
            if (valid1) {
                float y1 = p1 + cv;
                float q1 = 1.0f / (1.0f + expf(-y1));
                size_t off1 = (size_t)i1 * FOUT + o;
                outp[off1] = q1;
                outr[off1] = (q1 < cut) ? 0.0f : 1.0f;
            }
        }
        __syncthreads();
    }
}

// ---------------- launch ----------------
extern "C" void kernel_launch(void* const* d_in, const int* in_sizes, int n_in,
                              void* d_out, int out_size) {
    const float* x     = (const float*)d_in[0];
    const int*   edge  = (const int*)d_in[1];
    const float* W1    = (const float*)d_in[2];
    const float* b1    = (const float*)d_in[3];
    const float* gamma = (const float*)d_in[4];
    const float* beta  = (const float*)d_in[5];
    const float* W2    = (const float*)d_in[6];
    const float* b2    = (const float*)d_in[7];
    const float* Wl    = (const float*)d_in[8];
    const float* bl    = (const float*)d_in[9];
    const float* cut   = (const float*)d_in[10];

    int Ncur = in_sizes[0] / FIN;
    int Ecur = in_sizes[1] / 2;
    if (Ncur > NMAX || Ecur > EMAX || Ncur <= 0 || Ecur <= 0) return;

    const int* src = edge;
    const int* dst = edge + Ecur;
    float* outp = (float*)d_out;
    float* outr = outp + (size_t)out_size / 2;

    int nb = (Ncur + SCAN_BLK - 1) / SCAN_BLK;

    k_zero <<<(Ncur + 255) / 256, 256>>>(Ncur);
    k_count<<<(Ecur + 255) / 256, 256>>>(dst, Ecur);
    k_scan1<<<nb, SCAN_BLK>>>(Ncur);
    k_scan2<<<1, SCAN_BLK>>>(nb);
    k_scan3<<<(Ncur + 256) / 256, 256>>>(Ncur, Ecur);
    k_fill <<<(Ecur + 255) / 256, 256>>>(dst, Ecur);
    k_sort <<<(Ncur + 127) / 128, 128>>>(src, Ncur);
    k_ab   <<<(Ncur + 15) / 16, 128>>>(x, W1, Ncur);
    k_h1   <<<(Ncur * HID + 255) / 256, 256>>>(src, dst, Ncur);
    k_agg1 <<<Ncur, 128>>>();
    k_bnstats<<<STATS_BLOCKS, 128>>>(src, dst, b1, Ncur, Ecur);
    k_bnred<<<1, 128>>>(gamma, beta, Ecur);
    k_w2l  <<<64, 128>>>(Wl, W2, b2, bl);
    {
        int g = Ncur < 2048 ? Ncur : 2048;
        k_z<<<g, 128>>>(src, dst, b1, Ncur);
    }
    k_agg2 <<<Ncur, 64>>>();
    k_small<<<(Ncur * FOUT + 255) / 256, 256>>>(cut, outp, outr, Ncur);
    {
        int rows = Ecur - Ncur;
        if (rows > 0) {
            int pairs = (rows + 1) / 2;
            int g = pairs < 4096 ? pairs : 4096;
            k_final<<<g, 128>>>(src, dst, b1, cut, outp, outr, Ncur, Ecur);
        }
    }
}

// round 7
// speedup vs baseline: 1.3015x; 1.0431x over previous
#include <cuda_runtime.h>
#include <math.h>

// Problem constants (fixed shapes from reference setup_inputs)
#define NMAX 40000
#define EMAX 640000
#define HID  128
#define FIN  64
#define FOUT 64
#define STATS_BLOCKS 1024
#define STATS_BLOCKS_N 256
#define SCAN_BLK 256

// ---------------- device scratch (allocation-free: static globals) ----------------
__device__ float g_A[NMAX * HID];      // x @ W1a.T   [N,128]
__device__ float g_B[NMAX * HID];      // x @ W1b.T   [N,128]
__device__ float g_h1[NMAX * HID];     // h1 rows 0..N  (A[src]+B[dst])
__device__ float g_agg1[NMAX * HID];   // edge-aggregated h1
__device__ float g_wz[NMAX * FOUT];    // W2l @ r_j for j<N
__device__ float g_wa2[NMAX * FOUT];   // edge-aggregated wz
__device__ int   g_cnt[NMAX];
__device__ int   g_fill[NMAX];
__device__ int   g_rowptr[NMAX + 1];
__device__ int   g_bsum[(NMAX + SCAN_BLK - 1) / SCAN_BLK + 1];
__device__ int   g_eid[EMAX];
__device__ int   g_csrc[EMAX];
__device__ float g_cnorm[EMAX];
__device__ float g_dis[NMAX];
__device__ float g_invdeg[NMAX];
__device__ float g_part[(STATS_BLOCKS + STATS_BLOCKS_N) * 2 * HID];
__device__ float g_af[HID];
__device__ float g_cf[HID];
__device__ float g_W2l[FOUT * HID];    // Wl @ W2  [64,128]
__device__ float g_cvec[FOUT];         // Wl@b2 + bl

// ---------------- kernels ----------------

__global__ void k_zero(int Ncur) {
    int t = blockIdx.x * blockDim.x + threadIdx.x;
    if (t < Ncur) { g_cnt[t] = 0; g_fill[t] = 0; }
}

__global__ void k_count(const int* __restrict__ dst, int Ecur) {
    int e = blockIdx.x * blockDim.x + threadIdx.x;
    if (e < Ecur) atomicAdd(&g_cnt[dst[e]], 1);
}

// BN stats part E: rows i in [N, E) — pre = A[src]+B[dst]+b1. Heavy gather
// kernel, deliberately scheduled as launch index 3 so ncu profiles it.
__global__ void __launch_bounds__(128) k_bnstatsE(const int* __restrict__ src,
                                                  const int* __restrict__ dst,
                                                  const float* __restrict__ b1,
                                                  int Ncur, int Ecur) {
    int f = threadIdx.x;
    float bb = b1[f];
    float s_ = 0.f, q_ = 0.f;
    int stride = gridDim.x;
    int i = Ncur + blockIdx.x;
    int sn = (i < Ecur) ? src[i] : 0, dn = (i < Ecur) ? dst[i] : 0;
    while (i < Ecur) {
        int inext = i + stride;
        float vA = g_A[sn * HID + f];
        float vB = g_B[dn * HID + f];
        if (inext < Ecur) { sn = src[inext]; dn = dst[inext]; }
        float v = vA + vB + bb;
        s_ += v;
        q_ = fmaf(v, v, q_);
        i = inext;
    }
    g_part[blockIdx.x * (2 * HID) + f]       = s_;
    g_part[blockIdx.x * (2 * HID) + HID + f] = q_;
}

// BN stats part N: rows j in [0, N) — pre = invdeg*(A[src]+B[dst]) + agg1 + b1
__global__ void __launch_bounds__(128) k_bnstatsN(const int* __restrict__ src,
                                                  const int* __restrict__ dst,
                                                  const float* __restrict__ b1,
                                                  int Ncur) {
    int f = threadIdx.x;
    float bb = b1[f];
    float s_ = 0.f, q_ = 0.f;
    for (int j = blockIdx.x; j < Ncur; j += gridDim.x) {
        float v = g_invdeg[j] * (g_A[src[j] * HID + f] + g_B[dst[j] * HID + f])
                + g_agg1[j * HID + f] + bb;
        s_ += v;
        q_ = fmaf(v, v, q_);
    }
    size_t base = (size_t)(STATS_BLOCKS + blockIdx.x) * (2 * HID);
    g_part[base + f]       = s_;
    g_part[base + HID + f] = q_;
}

// scan pass 1: per-block exclusive scan + block totals; fused deg normalizers
__global__ void __launch_bounds__(SCAN_BLK) k_scan1(int Ncur) {
    __shared__ int sh[SCAN_BLK];
    int t = threadIdx.x;
    int idx = blockIdx.x * SCAN_BLK + t;
    int v = (idx < Ncur) ? g_cnt[idx] : 0;
    if (idx < Ncur) {
        float dg = (float)(v + 1);
        g_dis[idx]    = rsqrtf(dg);
        g_invdeg[idx] = 1.0f / dg;
    }
    sh[t] = v;
    __syncthreads();
#pragma unroll
    for (int off = 1; off < SCAN_BLK; off <<= 1) {
        int xv = (t >= off) ? sh[t - off] : 0;
        __syncthreads();
        sh[t] += xv;
        __syncthreads();
    }
    if (idx < Ncur) g_rowptr[idx] = sh[t] - v;
    if (t == SCAN_BLK - 1) g_bsum[blockIdx.x] = sh[t];
}

// scan pass 2: exclusive scan of block sums (nb <= SCAN_BLK)
__global__ void __launch_bounds__(SCAN_BLK) k_scan2(int nb) {
    __shared__ int sh[SCAN_BLK];
    int t = threadIdx.x;
    int v = (t < nb) ? g_bsum[t] : 0;
    sh[t] = v;
    __syncthreads();
#pragma unroll
    for (int off = 1; off < SCAN_BLK; off <<= 1) {
        int xv = (t >= off) ? sh[t - off] : 0;
        __syncthreads();
        sh[t] += xv;
        __syncthreads();
    }
    if (t < nb) g_bsum[t] = sh[t] - v;
}

// scan pass 3: apply block offsets; rowptr[N] = E
__global__ void k_scan3(int Ncur, int Ecur) {
    int idx = blockIdx.x * blockDim.x + threadIdx.x;
    if (idx < Ncur) g_rowptr[idx] += g_bsum[idx >> 8];
    if (idx == Ncur) g_rowptr[Ncur] = Ecur;
}

__global__ void k_fill(const int* __restrict__ dst, int Ecur) {
    int e = blockIdx.x * blockDim.x + threadIdx.x;
    if (e < Ecur) {
        int d = dst[e];
        int slot = g_rowptr[d] + atomicAdd(&g_fill[d], 1);
        g_eid[slot] = e;
    }
}

// sort each bucket by edge id (determinism), emit src + norm per slot.
// Buckets <= 64 sorted in a local (L1-resident) buffer.
__global__ void k_sort(const int* __restrict__ src, int Ncur) {
    int i = blockIdx.x * blockDim.x + threadIdx.x;
    if (i >= Ncur) return;
    int lo = g_rowptr[i], hi = g_rowptr[i + 1];
    int n = hi - lo;
    float di = g_dis[i];
    if (n <= 64) {
        int buf[64];
        for (int k = 0; k < n; k++) buf[k] = g_eid[lo + k];
        for (int a = 1; a < n; a++) {
            int key = buf[a];
            int b = a - 1;
            while (b >= 0 && buf[b] > key) { buf[b + 1] = buf[b]; b--; }
            buf[b + 1] = key;
        }
        for (int k = 0; k < n; k++) {
            int s = src[buf[k]];
            g_csrc[lo + k]  = s;
            g_cnorm[lo + k] = di * g_dis[s];
        }
    } else {
        for (int a = lo + 1; a < hi; a++) {
            int key = g_eid[a];
            int b = a - 1;
            while (b >= lo && g_eid[b] > key) { g_eid[b + 1] = g_eid[b]; b--; }
            g_eid[b + 1] = key;
        }
        for (int k = lo; k < hi; k++) {
            int s = src[g_eid[k]];
            g_csrc[k]  = s;
            g_cnorm[k] = di * g_dis[s];
        }
    }
}

// A = x @ W1[:, :64].T ; B = x @ W1[:, 64:].T   (16 nodes per block)
__global__ void __launch_bounds__(128) k_ab(const float* __restrict__ x,
                                            const float* __restrict__ W1, int Ncur) {
    __shared__ float xs[16][FIN];
    int j0 = blockIdx.x * 16;
    for (int idx = threadIdx.x; idx < 16 * FIN; idx += 128) {
        int j = idx >> 6, k = idx & 63;
        xs[j][k] = (j0 + j < Ncur) ? x[(j0 + j) * FIN + k] : 0.0f;
    }
    __syncthreads();
    int o = threadIdx.x;
    float accA[16], accB[16];
#pragma unroll
    for (int j = 0; j < 16; j++) { accA[j] = 0.f; accB[j] = 0.f; }
    const float* w = W1 + o * (2 * FIN);
    for (int k = 0; k < FIN; k++) {
        float wa = w[k], wb = w[FIN + k];
#pragma unroll
        for (int j = 0; j < 16; j++) {
            float xv = xs[j][k];
            accA[j] = fmaf(wa, xv, accA[j]);
            accB[j] = fmaf(wb, xv, accB[j]);
        }
    }
    for (int j = 0; j < 16; j++) {
        if (j0 + j < Ncur) {
            g_A[(j0 + j) * HID + o] = accA[j];
            g_B[(j0 + j) * HID + o] = accB[j];
        }
    }
}

// h1 rows 0..N-1: h1[j] = A[src[j]] + B[dst[j]]
__global__ void k_h1(const int* __restrict__ src, const int* __restrict__ dst, int Ncur) {
    int t = blockIdx.x * blockDim.x + threadIdx.x;
    if (t >= Ncur * HID) return;
    int j = t >> 7, f = t & 127;
    g_h1[t] = g_A[src[j] * HID + f] + g_B[dst[j] * HID + f];
}

// agg1[i] = sum over CSR bucket i of norm * h1[src]; indices staged in smem
__global__ void __launch_bounds__(128) k_agg1() {
    __shared__ int   ssrc[128];
    __shared__ float snorm[128];
    int i = blockIdx.x, f = threadIdx.x;
    int lo = g_rowptr[i], hi = g_rowptr[i + 1];
    float acc = 0.f;
    for (int base = lo; base < hi; base += 128) {
        int m = hi - base; if (m > 128) m = 128;
        if (f < m) { ssrc[f] = g_csrc[base + f]; snorm[f] = g_cnorm[base + f]; }
        __syncthreads();
        int k = 0;
        for (; k + 4 <= m; k += 4) {
            int s0 = ssrc[k], s1 = ssrc[k + 1], s2 = ssrc[k + 2], s3 = ssrc[k + 3];
            float n0 = snorm[k], n1 = snorm[k + 1], n2 = snorm[k + 2], n3 = snorm[k + 3];
            float v0 = g_h1[s0 * HID + f], v1 = g_h1[s1 * HID + f];
            float v2 = g_h1[s2 * HID + f], v3 = g_h1[s3 * HID + f];
            acc = fmaf(n0, v0, acc); acc = fmaf(n1, v1, acc);
            acc = fmaf(n2, v2, acc); acc = fmaf(n3, v3, acc);
        }
        for (; k < m; k++) acc = fmaf(snorm[k], g_h1[ssrc[k] * HID + f], acc);
        __syncthreads();
    }
    g_agg1[i * HID + f] = acc;
}

// finalize BN over both partial regions (fixed-order reduce -> deterministic)
__global__ void k_bnred(const float* __restrict__ gamma, const float* __restrict__ beta, int Ecur) {
    int f = threadIdx.x;
    float s = 0.f, q = 0.f;
    for (int b = 0; b < STATS_BLOCKS + STATS_BLOCKS_N; b++) {
        s += g_part[(size_t)b * (2 * HID) + f];
        q += g_part[(size_t)b * (2 * HID) + HID + f];
    }
    float invE = 1.0f / (float)Ecur;
    float mu  = s * invE;
    float var = q * invE - mu * mu;
    float istd = rsqrtf(var + 1e-5f);
    float a = gamma[f] * istd;
    g_af[f] = a;
    g_cf[f] = beta[f] - mu * a;
}

// W2l = Wl @ W2 ; cvec = Wl@b2 + bl
__global__ void k_w2l(const float* __restrict__ Wl, const float* __restrict__ W2,
                      const float* __restrict__ b2, const float* __restrict__ bl) {
    int t = blockIdx.x * blockDim.x + threadIdx.x;  // 8192 threads
    int o = t >> 7, f = t & 127;
    float acc = 0.f;
#pragma unroll
    for (int m = 0; m < 64; m++) acc = fmaf(Wl[o * 64 + m], W2[m * HID + f], acc);
    g_W2l[t] = acc;
    if (t < 64) {
        float cv = 0.f;
        for (int m = 0; m < 64; m++) cv = fmaf(Wl[t * 64 + m], b2[m], cv);
        g_cvec[t] = cv + bl[t];
    }
}

// wz[j] = W2l @ relu(bn(pre_j)) for j < N   (needed by aggregation 2)
__global__ void __launch_bounds__(128) k_z(const int* __restrict__ src,
                                           const int* __restrict__ dst,
                                           const float* __restrict__ b1, int Ncur) {
    int f = threadIdx.x;
    float bb = b1[f], af = g_af[f], cf = g_cf[f];
    int o = f & 63, h = f >> 6;
    float wreg[64];
#pragma unroll
    for (int k = 0; k < 64; k++) wreg[k] = g_W2l[o * HID + h * 64 + k];
    __shared__ __align__(16) float rsh[HID];
    __shared__ float ps[64];
    for (int j = blockIdx.x; j < Ncur; j += gridDim.x) {
        int s = src[j], d = dst[j];
        float v = g_A[s * HID + f] + g_B[d * HID + f];
        v = g_invdeg[j] * v + g_agg1[j * HID + f] + bb;
        rsh[f] = fmaxf(fmaf(af, v, cf), 0.f);
        __syncthreads();
        const float4* r4 = (const float4*)(rsh + h * 64);
        float a0 = 0.f, a1 = 0.f, a2 = 0.f, a3 = 0.f;
#pragma unroll
        for (int k = 0; k < 16; k++) {
            float4 rv = r4[k];
            a0 = fmaf(wreg[4 * k + 0], rv.x, a0);
            a1 = fmaf(wreg[4 * k + 1], rv.y, a1);
            a2 = fmaf(wreg[4 * k + 2], rv.z, a2);
            a3 = fmaf(wreg[4 * k + 3], rv.w, a3);
        }
        float part = (a0 + a1) + (a2 + a3);
        if (h) ps[o] = part;
        __syncthreads();
        if (!h) g_wz[j * FOUT + o] = part + ps[o];
        __syncthreads();
    }
}

// wa2[i] = sum over bucket i of norm * wz[src]; indices staged in smem
__global__ void __launch_bounds__(64) k_agg2() {
    __shared__ int   ssrc[64];
    __shared__ float snorm[64];
    int i = blockIdx.x, f = threadIdx.x;
    int lo = g_rowptr[i], hi = g_rowptr[i + 1];
    float acc = 0.f;
    for (int base = lo; base < hi; base += 64) {
        int m = hi - base; if (m > 64) m = 64;
        if (f < m) { ssrc[f] = g_csrc[base + f]; snorm[f] = g_cnorm[base + f]; }
        __syncthreads();
        int k = 0;
        for (; k + 4 <= m; k += 4) {
            int s0 = ssrc[k], s1 = ssrc[k + 1], s2 = ssrc[k + 2], s3 = ssrc[k + 3];
            float n0 = snorm[k], n1 = snorm[k + 1], n2 = snorm[k + 2], n3 = snorm[k + 3];
            float v0 = g_wz[s0 * FOUT + f], v1 = g_wz[s1 * FOUT + f];
            float v2 = g_wz[s2 * FOUT + f], v3 = g_wz[s3 * FOUT + f];
            acc = fmaf(n0, v0, acc); acc = fmaf(n1, v1, acc);
            acc = fmaf(n2, v2, acc); acc = fmaf(n3, v3, acc);
        }
        for (; k < m; k++) acc = fmaf(snorm[k], g_wz[ssrc[k] * FOUT + f], acc);
        __syncthreads();
    }
    g_wa2[i * FOUT + f] = acc;
}

// rows i < N: y = invdeg*wz + wa2 + cvec  (pure elementwise)
__global__ void k_small(const float* __restrict__ cutp, float* __restrict__ outp,
                        float* __restrict__ outr, int Ncur) {
    int t = blockIdx.x * blockDim.x + threadIdx.x;
    if (t >= Ncur * FOUT) return;
    int i = t >> 6, o = t & 63;
    float y = g_invdeg[i] * g_wz[t] + g_wa2[t] + g_cvec[o];
    float p = 1.0f / (1.0f + expf(-y));
    outp[t] = p;
    outr[t] = (p < *cutp) ? 0.0f : 1.0f;
}

// rows i in [N, E): full matvec + sigmoid + threshold (R4-proven version)
__global__ void __launch_bounds__(128) k_final(const int* __restrict__ src,
                                               const int* __restrict__ dst,
                                               const float* __restrict__ b1,
                                               const float* __restrict__ cutp,
                                               float* __restrict__ outp,
                                               float* __restrict__ outr,
                                               int Ncur, int Ecur) {
    int f = threadIdx.x;
    float bb = b1[f], af = g_af[f], cf = g_cf[f];
    int o = f & 63, h = f >> 6;
    float wreg[64];
#pragma unroll
    for (int k = 0; k < 64; k++) wreg[k] = g_W2l[o * HID + h * 64 + k];
    float cv  = g_cvec[o];
    float cut = *cutp;
    __shared__ __align__(16) float rsh[HID];
    __shared__ float ps[64];
    int i = Ncur + blockIdx.x;
    if (i >= Ecur) return;
    int s = src[i], d = dst[i];
    while (i < Ecur) {
        int inext = i + gridDim.x;
        float vA = g_A[s * HID + f];
        float vB = g_B[d * HID + f];
        if (inext < Ecur) { s = src[inext]; d = dst[inext]; }
        float v = vA + vB + bb;
        rsh[f] = fmaxf(fmaf(af, v, cf), 0.f);
        __syncthreads();
        const float4* r4 = (const float4*)(rsh + h * 64);
        float a0 = 0.f, a1 = 0.f, a2 = 0.f, a3 = 0.f;
#pragma unroll
        for (int k = 0; k < 16; k++) {
            float4 rv = r4[k];
            a0 = fmaf(wreg[4 * k + 0], rv.x, a0);
            a1 = fmaf(wreg[4 * k + 1], rv.y, a1);
            a2 = fmaf(wreg[4 * k + 2], rv.z, a2);
            a3 = fmaf(wreg[4 * k + 3], rv.w, a3);
        }
        float part = (a0 + a1) + (a2 + a3);
        if (h) ps[o] = part;
        __syncthreads();
        if (!h) {
            float y = (part + ps[o]) + cv;
            float p = 1.0f / (1.0f + expf(-y));
            size_t off = (size_t)i * FOUT + o;
            outp[off] = p;
            outr[off] = (p < cut) ? 0.0f : 1.0f;
        }
        __syncthreads();
        i = inext;
    }
}

// ---------------- launch ----------------
extern "C" void kernel_launch(void* const* d_in, const int* in_sizes, int n_in,
                              void* d_out, int out_size) {
    const float* x     = (const float*)d_in[0];
    const int*   edge  = (const int*)d_in[1];
    const float* W1    = (const float*)d_in[2];
    const float* b1    = (const float*)d_in[3];
    const float* gamma = (const float*)d_in[4];
    const float* beta  = (const float*)d_in[5];
    const float* W2    = (const float*)d_in[6];
    const float* b2    = (const float*)d_in[7];
    const float* Wl    = (const float*)d_in[8];
    const float* bl    = (const float*)d_in[9];
    const float* cut   = (const float*)d_in[10];

    int Ncur = in_sizes[0] / FIN;
    int Ecur = in_sizes[1] / 2;
    if (Ncur > NMAX || Ecur > EMAX || Ncur <= 0 || Ecur <= 0) return;

    const int* src = edge;
    const int* dst = edge + Ecur;
    float* outp = (float*)d_out;
    float* outr = outp + (size_t)out_size / 2;

    int nb = (Ncur + SCAN_BLK - 1) / SCAN_BLK;

    // Launch order puts k_bnstatsE (heavy gather kernel) at index 3,
    // where the harness's ncu capture window lands.
    k_ab       <<<(Ncur + 15) / 16, 128>>>(x, W1, Ncur);           // 0
    k_zero     <<<(Ncur + 255) / 256, 256>>>(Ncur);                // 1
    k_count    <<<(Ecur + 255) / 256, 256>>>(dst, Ecur);           // 2
    k_bnstatsE <<<STATS_BLOCKS, 128>>>(src, dst, b1, Ncur, Ecur);  // 3 (profiled)
    k_scan1    <<<nb, SCAN_BLK>>>(Ncur);                           // 4
    k_scan2    <<<1, SCAN_BLK>>>(nb);                              // 5
    k_scan3    <<<(Ncur + 256) / 256, 256>>>(Ncur, Ecur);          // 6
    k_fill     <<<(Ecur + 255) / 256, 256>>>(dst, Ecur);           // 7
    k_sort     <<<(Ncur + 127) / 128, 128>>>(src, Ncur);           // 8
    k_h1       <<<(Ncur * HID + 255) / 256, 256>>>(src, dst, Ncur);// 9
    k_agg1     <<<Ncur, 128>>>();                                  // 10
    k_bnstatsN <<<STATS_BLOCKS_N, 128>>>(src, dst, b1, Ncur);      // 11
    k_bnred    <<<1, 128>>>(gamma, beta, Ecur);                    // 12
    k_w2l      <<<64, 128>>>(Wl, W2, b2, bl);                      // 13
    {
        int g = Ncur < 2048 ? Ncur : 2048;
        k_z<<<g, 128>>>(src, dst, b1, Ncur);                       // 14
    }
    k_agg2     <<<Ncur, 64>>>();                                   // 15
    k_small    <<<(Ncur * FOUT + 255) / 256, 256>>>(cut, outp, outr, Ncur); // 16
    {
        int rows = Ecur - Ncur;
        if (rows > 0) {
            int g = rows < 4096 ? rows : 4096;
            k_final<<<g, 128>>>(src, dst, b1, cut, outp, outr, Ncur, Ecur); // 17
        }
    }
}

// round 8
// speedup vs baseline: 1.4816x; 1.1384x over previous
#include <cuda_runtime.h>
#include <math.h>

// Problem constants (fixed shapes from reference setup_inputs)
#define NMAX 40000
#define EMAX 640000
#define HID  128
#define FIN  64
#define FOUT 64
#define STATS_BLOCKS 1024
#define STATS_BLOCKS_N 256
#define SCAN_BLK 256

// ---------------- device scratch (allocation-free: static globals) ----------------
__device__ float g_A[NMAX * HID];      // x @ W1a.T   [N,128]
__device__ float g_B[NMAX * HID];      // x @ W1b.T   [N,128]
__device__ float g_h1[NMAX * HID];     // h1 rows 0..N  (A[src]+B[dst])
__device__ float g_agg1[NMAX * HID];   // edge-aggregated h1
__device__ float g_wz[NMAX * FOUT];    // W2l @ r_j for j<N
__device__ float g_wa2[NMAX * FOUT];   // edge-aggregated wz
__device__ int   g_cnt[NMAX];
__device__ int   g_fill[NMAX];
__device__ int   g_rowptr[NMAX + 1];
__device__ int   g_bsum[(NMAX + SCAN_BLK - 1) / SCAN_BLK + 1];
__device__ int   g_eid[EMAX];
__device__ int   g_csrc[EMAX];
__device__ float g_cnorm[EMAX];
__device__ float g_dis[NMAX];
__device__ float g_invdeg[NMAX];
__device__ float g_part[(STATS_BLOCKS + STATS_BLOCKS_N) * 2 * HID];
__device__ float g_af[HID];
__device__ float g_cf[HID];
__device__ float g_W2l[FOUT * HID];    // Wl @ W2  [64,128]
__device__ float g_cvec[FOUT];         // Wl@b2 + bl

// ---------------- kernels ----------------

__global__ void k_zero(int Ncur) {
    int t = blockIdx.x * blockDim.x + threadIdx.x;
    if (t < Ncur) { g_cnt[t] = 0; g_fill[t] = 0; }
}

__global__ void k_count(const int* __restrict__ dst, int Ecur) {
    int e = blockIdx.x * blockDim.x + threadIdx.x;
    if (e < Ecur) atomicAdd(&g_cnt[dst[e]], 1);
}

// BN stats part E: rows i in [N, E) — pre = A[src]+B[dst]+b1.
// 4 rows per iteration: 8 independent row-gather loads in flight (MLP fix).
__global__ void __launch_bounds__(128) k_bnstatsE(const int* __restrict__ src,
                                                  const int* __restrict__ dst,
                                                  const float* __restrict__ b1,
                                                  int Ncur, int Ecur) {
    int f = threadIdx.x;
    float bb = b1[f];
    float s_ = 0.f, q_ = 0.f;
    int stride = gridDim.x * 4;
    for (int i = Ncur + blockIdx.x * 4; i < Ecur; i += stride) {
        int n = Ecur - i; if (n > 4) n = 4;
        int sn[4], dn[4];
#pragma unroll
        for (int k = 0; k < 4; k++) {
            int ii = (k < n) ? (i + k) : i;
            sn[k] = src[ii];
            dn[k] = dst[ii];
        }
        float vA[4], vB[4];
#pragma unroll
        for (int k = 0; k < 4; k++) {
            vA[k] = g_A[sn[k] * HID + f];
            vB[k] = g_B[dn[k] * HID + f];
        }
#pragma unroll
        for (int k = 0; k < 4; k++) {
            if (k < n) {
                float v = vA[k] + vB[k] + bb;
                s_ += v;
                q_ = fmaf(v, v, q_);
            }
        }
    }
    g_part[blockIdx.x * (2 * HID) + f]       = s_;
    g_part[blockIdx.x * (2 * HID) + HID + f] = q_;
}

// BN stats part N: rows j in [0, N) — pre = invdeg*(A[src]+B[dst]) + agg1 + b1
// Same 4-row unroll.
__global__ void __launch_bounds__(128) k_bnstatsN(const int* __restrict__ src,
                                                  const int* __restrict__ dst,
                                                  const float* __restrict__ b1,
                                                  int Ncur) {
    int f = threadIdx.x;
    float bb = b1[f];
    float s_ = 0.f, q_ = 0.f;
    int stride = gridDim.x * 4;
    for (int j = blockIdx.x * 4; j < Ncur; j += stride) {
        int n = Ncur - j; if (n > 4) n = 4;
        int sn[4], dn[4];
#pragma unroll
        for (int k = 0; k < 4; k++) {
            int jj = (k < n) ? (j + k) : j;
            sn[k] = src[jj];
            dn[k] = dst[jj];
        }
        float vA[4], vB[4], ag[4], idg[4];
#pragma unroll
        for (int k = 0; k < 4; k++) {
            int jj = (k < n) ? (j + k) : j;
            vA[k]  = g_A[sn[k] * HID + f];
            vB[k]  = g_B[dn[k] * HID + f];
            ag[k]  = g_agg1[jj * HID + f];
            idg[k] = g_invdeg[jj];
        }
#pragma unroll
        for (int k = 0; k < 4; k++) {
            if (k < n) {
                float v = idg[k] * (vA[k] + vB[k]) + ag[k] + bb;
                s_ += v;
                q_ = fmaf(v, v, q_);
            }
        }
    }
    size_t base = (size_t)(STATS_BLOCKS + blockIdx.x) * (2 * HID);
    g_part[base + f]       = s_;
    g_part[base + HID + f] = q_;
}

// scan pass 1: per-block exclusive scan + block totals; fused deg normalizers
__global__ void __launch_bounds__(SCAN_BLK) k_scan1(int Ncur) {
    __shared__ int sh[SCAN_BLK];
    int t = threadIdx.x;
    int idx = blockIdx.x * SCAN_BLK + t;
    int v = (idx < Ncur) ? g_cnt[idx] : 0;
    if (idx < Ncur) {
        float dg = (float)(v + 1);
        g_dis[idx]    = rsqrtf(dg);
        g_invdeg[idx] = 1.0f / dg;
    }
    sh[t] = v;
    __syncthreads();
#pragma unroll
    for (int off = 1; off < SCAN_BLK; off <<= 1) {
        int xv = (t >= off) ? sh[t - off] : 0;
        __syncthreads();
        sh[t] += xv;
        __syncthreads();
    }
    if (idx < Ncur) g_rowptr[idx] = sh[t] - v;
    if (t == SCAN_BLK - 1) g_bsum[blockIdx.x] = sh[t];
}

// scan pass 2: exclusive scan of block sums (nb <= SCAN_BLK)
__global__ void __launch_bounds__(SCAN_BLK) k_scan2(int nb) {
    __shared__ int sh[SCAN_BLK];
    int t = threadIdx.x;
    int v = (t < nb) ? g_bsum[t] : 0;
    sh[t] = v;
    __syncthreads();
#pragma unroll
    for (int off = 1; off < SCAN_BLK; off <<= 1) {
        int xv = (t >= off) ? sh[t - off] : 0;
        __syncthreads();
        sh[t] += xv;
        __syncthreads();
    }
    if (t < nb) g_bsum[t] = sh[t] - v;
}

// scan pass 3: apply block offsets; rowptr[N] = E
__global__ void k_scan3(int Ncur, int Ecur) {
    int idx = blockIdx.x * blockDim.x + threadIdx.x;
    if (idx < Ncur) g_rowptr[idx] += g_bsum[idx >> 8];
    if (idx == Ncur) g_rowptr[Ncur] = Ecur;
}

__global__ void k_fill(const int* __restrict__ dst, int Ecur) {
    int e = blockIdx.x * blockDim.x + threadIdx.x;
    if (e < Ecur) {
        int d = dst[e];
        int slot = g_rowptr[d] + atomicAdd(&g_fill[d], 1);
        g_eid[slot] = e;
    }
}

// sort each bucket by edge id (determinism), emit src + norm per slot.
// Buckets <= 64 sorted in a local (L1-resident) buffer.
__global__ void k_sort(const int* __restrict__ src, int Ncur) {
    int i = blockIdx.x * blockDim.x + threadIdx.x;
    if (i >= Ncur) return;
    int lo = g_rowptr[i], hi = g_rowptr[i + 1];
    int n = hi - lo;
    float di = g_dis[i];
    if (n <= 64) {
        int buf[64];
        for (int k = 0; k < n; k++) buf[k] = g_eid[lo + k];
        for (int a = 1; a < n; a++) {
            int key = buf[a];
            int b = a - 1;
            while (b >= 0 && buf[b] > key) { buf[b + 1] = buf[b]; b--; }
            buf[b + 1] = key;
        }
        for (int k = 0; k < n; k++) {
            int s = src[buf[k]];
            g_csrc[lo + k]  = s;
            g_cnorm[lo + k] = di * g_dis[s];
        }
    } else {
        for (int a = lo + 1; a < hi; a++) {
            int key = g_eid[a];
            int b = a - 1;
            while (b >= lo && g_eid[b] > key) { g_eid[b + 1] = g_eid[b]; b--; }
            g_eid[b + 1] = key;
        }
        for (int k = lo; k < hi; k++) {
            int s = src[g_eid[k]];
            g_csrc[k]  = s;
            g_cnorm[k] = di * g_dis[s];
        }
    }
}

// A = x @ W1[:, :64].T ; B = x @ W1[:, 64:].T   (16 nodes per block)
__global__ void __launch_bounds__(128) k_ab(const float* __restrict__ x,
                                            const float* __restrict__ W1, int Ncur) {
    __shared__ float xs[16][FIN];
    int j0 = blockIdx.x * 16;
    for (int idx = threadIdx.x; idx < 16 * FIN; idx += 128) {
        int j = idx >> 6, k = idx & 63;
        xs[j][k] = (j0 + j < Ncur) ? x[(j0 + j) * FIN + k] : 0.0f;
    }
    __syncthreads();
    int o = threadIdx.x;
    float accA[16], accB[16];
#pragma unroll
    for (int j = 0; j < 16; j++) { accA[j] = 0.f; accB[j] = 0.f; }
    const float* w = W1 + o * (2 * FIN);
    for (int k = 0; k < FIN; k++) {
        float wa = w[k], wb = w[FIN + k];
#pragma unroll
        for (int j = 0; j < 16; j++) {
            float xv = xs[j][k];
            accA[j] = fmaf(wa, xv, accA[j]);
            accB[j] = fmaf(wb, xv, accB[j]);
        }
    }
    for (int j = 0; j < 16; j++) {
        if (j0 + j < Ncur) {
            g_A[(j0 + j) * HID + o] = accA[j];
            g_B[(j0 + j) * HID + o] = accB[j];
        }
    }
}

// h1 rows 0..N-1: h1[j] = A[src[j]] + B[dst[j]]
__global__ void k_h1(const int* __restrict__ src, const int* __restrict__ dst, int Ncur) {
    int t = blockIdx.x * blockDim.x + threadIdx.x;
    if (t >= Ncur * HID) return;
    int j = t >> 7, f = t & 127;
    g_h1[t] = g_A[src[j] * HID + f] + g_B[dst[j] * HID + f];
}

// agg1[i] = sum over CSR bucket i of norm * h1[src]; indices staged in smem
__global__ void __launch_bounds__(128) k_agg1() {
    __shared__ int   ssrc[128];
    __shared__ float snorm[128];
    int i = blockIdx.x, f = threadIdx.x;
    int lo = g_rowptr[i], hi = g_rowptr[i + 1];
    float acc = 0.f;
    for (int base = lo; base < hi; base += 128) {
        int m = hi - base; if (m > 128) m = 128;
        if (f < m) { ssrc[f] = g_csrc[base + f]; snorm[f] = g_cnorm[base + f]; }
        __syncthreads();
        int k = 0;
        for (; k + 4 <= m; k += 4) {
            int s0 = ssrc[k], s1 = ssrc[k + 1], s2 = ssrc[k + 2], s3 = ssrc[k + 3];
            float n0 = snorm[k], n1 = snorm[k + 1], n2 = snorm[k + 2], n3 = snorm[k + 3];
            float v0 = g_h1[s0 * HID + f], v1 = g_h1[s1 * HID + f];
            float v2 = g_h1[s2 * HID + f], v3 = g_h1[s3 * HID + f];
            acc = fmaf(n0, v0, acc); acc = fmaf(n1, v1, acc);
            acc = fmaf(n2, v2, acc); acc = fmaf(n3, v3, acc);
        }
        for (; k < m; k++) acc = fmaf(snorm[k], g_h1[ssrc[k] * HID + f], acc);
        __syncthreads();
    }
    g_agg1[i * HID + f] = acc;
}

// finalize BN over both partial regions (fixed-order reduce -> deterministic)
__global__ void k_bnred(const float* __restrict__ gamma, const float* __restrict__ beta, int Ecur) {
    int f = threadIdx.x;
    float s = 0.f, q = 0.f;
    for (int b = 0; b < STATS_BLOCKS + STATS_BLOCKS_N; b++) {
        s += g_part[(size_t)b * (2 * HID) + f];
        q += g_part[(size_t)b * (2 * HID) + HID + f];
    }
    float invE = 1.0f / (float)Ecur;
    float mu  = s * invE;
    float var = q * invE - mu * mu;
    float istd = rsqrtf(var + 1e-5f);
    float a = gamma[f] * istd;
    g_af[f] = a;
    g_cf[f] = beta[f] - mu * a;
}

// W2l = Wl @ W2 ; cvec = Wl@b2 + bl
__global__ void k_w2l(const float* __restrict__ Wl, const float* __restrict__ W2,
                      const float* __restrict__ b2, const float* __restrict__ bl) {
    int t = blockIdx.x * blockDim.x + threadIdx.x;  // 8192 threads
    int o = t >> 7, f = t & 127;
    float acc = 0.f;
#pragma unroll
    for (int m = 0; m < 64; m++) acc = fmaf(Wl[o * 64 + m], W2[m * HID + f], acc);
    g_W2l[t] = acc;
    if (t < 64) {
        float cv = 0.f;
        for (int m = 0; m < 64; m++) cv = fmaf(Wl[t * 64 + m], b2[m], cv);
        g_cvec[t] = cv + bl[t];
    }
}

// wz[j] = W2l @ relu(bn(pre_j)) for j < N   (needed by aggregation 2)
__global__ void __launch_bounds__(128) k_z(const int* __restrict__ src,
                                           const int* __restrict__ dst,
                                           const float* __restrict__ b1, int Ncur) {
    int f = threadIdx.x;
    float bb = b1[f], af = g_af[f], cf = g_cf[f];
    int o = f & 63, h = f >> 6;
    float wreg[64];
#pragma unroll
    for (int k = 0; k < 64; k++) wreg[k] = g_W2l[o * HID + h * 64 + k];
    __shared__ __align__(16) float rsh[HID];
    __shared__ float ps[64];
    for (int j = blockIdx.x; j < Ncur; j += gridDim.x) {
        int s = src[j], d = dst[j];
        float v = g_A[s * HID + f] + g_B[d * HID + f];
        v = g_invdeg[j] * v + g_agg1[j * HID + f] + bb;
        rsh[f] = fmaxf(fmaf(af, v, cf), 0.f);
        __syncthreads();
        const float4* r4 = (const float4*)(rsh + h * 64);
        float a0 = 0.f, a1 = 0.f, a2 = 0.f, a3 = 0.f;
#pragma unroll
        for (int k = 0; k < 16; k++) {
            float4 rv = r4[k];
            a0 = fmaf(wreg[4 * k + 0], rv.x, a0);
            a1 = fmaf(wreg[4 * k + 1], rv.y, a1);
            a2 = fmaf(wreg[4 * k + 2], rv.z, a2);
            a3 = fmaf(wreg[4 * k + 3], rv.w, a3);
        }
        float part = (a0 + a1) + (a2 + a3);
        if (h) ps[o] = part;
        __syncthreads();
        if (!h) g_wz[j * FOUT + o] = part + ps[o];
        __syncthreads();
    }
}

// wa2[i] = sum over bucket i of norm * wz[src]; indices staged in smem
__global__ void __launch_bounds__(64) k_agg2() {
    __shared__ int   ssrc[64];
    __shared__ float snorm[64];
    int i = blockIdx.x, f = threadIdx.x;
    int lo = g_rowptr[i], hi = g_rowptr[i + 1];
    float acc = 0.f;
    for (int base = lo; base < hi; base += 64) {
        int m = hi - base; if (m > 64) m = 64;
        if (f < m) { ssrc[f] = g_csrc[base + f]; snorm[f] = g_cnorm[base + f]; }
        __syncthreads();
        int k = 0;
        for (; k + 4 <= m; k += 4) {
            int s0 = ssrc[k], s1 = ssrc[k + 1], s2 = ssrc[k + 2], s3 = ssrc[k + 3];
            float n0 = snorm[k], n1 = snorm[k + 1], n2 = snorm[k + 2], n3 = snorm[k + 3];
            float v0 = g_wz[s0 * FOUT + f], v1 = g_wz[s1 * FOUT + f];
            float v2 = g_wz[s2 * FOUT + f], v3 = g_wz[s3 * FOUT + f];
            acc = fmaf(n0, v0, acc); acc = fmaf(n1, v1, acc);
            acc = fmaf(n2, v2, acc); acc = fmaf(n3, v3, acc);
        }
        for (; k < m; k++) acc = fmaf(snorm[k], g_wz[ssrc[k] * FOUT + f], acc);
        __syncthreads();
    }
    g_wa2[i * FOUT + f] = acc;
}

// rows i < N: y = invdeg*wz + wa2 + cvec  (pure elementwise)
__global__ void k_small(const float* __restrict__ cutp, float* __restrict__ outp,
                        float* __restrict__ outr, int Ncur) {
    int t = blockIdx.x * blockDim.x + threadIdx.x;
    if (t >= Ncur * FOUT) return;
    int i = t >> 6, o = t & 63;
    float y = g_invdeg[i] * g_wz[t] + g_wa2[t] + g_cvec[o];
    float p = 1.0f / (1.0f + expf(-y));
    outp[t] = p;
    outr[t] = (p < *cutp) ? 0.0f : 1.0f;
}

// rows i in [N, E): full matvec + sigmoid + threshold (R4-proven version)
__global__ void __launch_bounds__(128) k_final(const int* __restrict__ src,
                                               const int* __restrict__ dst,
                                               const float* __restrict__ b1,
                                               const float* __restrict__ cutp,
                                               float* __restrict__ outp,
                                               float* __restrict__ outr,
                                               int Ncur, int Ecur) {
    int f = threadIdx.x;
    float bb = b1[f], af = g_af[f], cf = g_cf[f];
    int o = f & 63, h = f >> 6;
    float wreg[64];
#pragma unroll
    for (int k = 0; k < 64; k++) wreg[k] = g_W2l[o * HID + h * 64 + k];
    float cv  = g_cvec[o];
    float cut = *cutp;
    __shared__ __align__(16) float rsh[HID];
    __shared__ float ps[64];
    int i = Ncur + blockIdx.x;
    if (i >= Ecur) return;
    int s = src[i], d = dst[i];
    while (i < Ecur) {
        int inext = i + gridDim.x;
        float vA = g_A[s * HID + f];
        float vB = g_B[d * HID + f];
        if (inext < Ecur) { s = src[inext]; d = dst[inext]; }
        float v = vA + vB + bb;
        rsh[f] = fmaxf(fmaf(af, v, cf), 0.f);
        __syncthreads();
        const float4* r4 = (const float4*)(rsh + h * 64);
        float a0 = 0.f, a1 = 0.f, a2 = 0.f, a3 = 0.f;
#pragma unroll
        for (int k = 0; k < 16; k++) {
            float4 rv = r4[k];
            a0 = fmaf(wreg[4 * k + 0], rv.x, a0);
            a1 = fmaf(wreg[4 * k + 1], rv.y, a1);
            a2 = fmaf(wreg[4 * k + 2], rv.z, a2);
            a3 = fmaf(wreg[4 * k + 3], rv.w, a3);
        }
        float part = (a0 + a1) + (a2 + a3);
        if (h) ps[o] = part;
        __syncthreads();
        if (!h) {
            float y = (part + ps[o]) + cv;
            float p = 1.0f / (1.0f + expf(-y));
            size_t off = (size_t)i * FOUT + o;
            outp[off] = p;
            outr[off] = (p < cut) ? 0.0f : 1.0f;
        }
        __syncthreads();
        i = inext;
    }
}

// ---------------- launch ----------------
extern "C" void kernel_launch(void* const* d_in, const int* in_sizes, int n_in,
                              void* d_out, int out_size) {
    const float* x     = (const float*)d_in[0];
    const int*   edge  = (const int*)d_in[1];
    const float* W1    = (const float*)d_in[2];
    const float* b1    = (const float*)d_in[3];
    const float* gamma = (const float*)d_in[4];
    const float* beta  = (const float*)d_in[5];
    const float* W2    = (const float*)d_in[6];
    const float* b2    = (const float*)d_in[7];
    const float* Wl    = (const float*)d_in[8];
    const float* bl    = (const float*)d_in[9];
    const float* cut   = (const float*)d_in[10];

    int Ncur = in_sizes[0] / FIN;
    int Ecur = in_sizes[1] / 2;
    if (Ncur > NMAX || Ecur > EMAX || Ncur <= 0 || Ecur <= 0) return;

    const int* src = edge;
    const int* dst = edge + Ecur;
    float* outp = (float*)d_out;
    float* outr = outp + (size_t)out_size / 2;

    int nb = (Ncur + SCAN_BLK - 1) / SCAN_BLK;

    // Launch order keeps k_bnstatsE at index 3 (ncu capture window) to
    // verify the MLP-unroll prediction: 281us -> ~80-100us.
    k_ab       <<<(Ncur + 15) / 16, 128>>>(x, W1, Ncur);           // 0
    k_zero     <<<(Ncur + 255) / 256, 256>>>(Ncur);                // 1
    k_count    <<<(Ecur + 255) / 256, 256>>>(dst, Ecur);           // 2
    k_bnstatsE <<<STATS_BLOCKS, 128>>>(src, dst, b1, Ncur, Ecur);  // 3 (profiled)
    k_scan1    <<<nb, SCAN_BLK>>>(Ncur);                           // 4
    k_scan2    <<<1, SCAN_BLK>>>(nb);                              // 5
    k_scan3    <<<(Ncur + 256) / 256, 256>>>(Ncur, Ecur);          // 6
    k_fill     <<<(Ecur + 255) / 256, 256>>>(dst, Ecur);           // 7
    k_sort     <<<(Ncur + 127) / 128, 128>>>(src, Ncur);           // 8
    k_h1       <<<(Ncur * HID + 255) / 256, 256>>>(src, dst, Ncur);// 9
    k_agg1     <<<Ncur, 128>>>();                                  // 10
    k_bnstatsN <<<STATS_BLOCKS_N, 128>>>(src, dst, b1, Ncur);      // 11
    k_bnred    <<<1, 128>>>(gamma, beta, Ecur);                    // 12
    k_w2l      <<<64, 128>>>(Wl, W2, b2, bl);                      // 13
    {
        int g = Ncur < 2048 ? Ncur : 2048;
        k_z<<<g, 128>>>(src, dst, b1, Ncur);                       // 14
    }
    k_agg2     <<<Ncur, 64>>>();                                   // 15
    k_small    <<<(Ncur * FOUT + 255) / 256, 256>>>(cut, outp, outr, Ncur); // 16
    {
        int rows = Ecur - Ncur;
        if (rows > 0) {
            int g = rows < 4096 ? rows : 4096;
            k_final<<<g, 128>>>(src, dst, b1, cut, outp, outr, Ncur, Ecur); // 17
        }
    }
}

// round 9
// speedup vs baseline: 1.6752x; 1.1307x over previous
#include <cuda_runtime.h>
#include <math.h>

// Problem constants (fixed shapes from reference setup_inputs)
#define NMAX 40000
#define EMAX 640000
#define HID  128
#define FIN  64
#define FOUT 64
#define STATS_BLOCKS 1024
#define STATS_BLOCKS_N 256
#define SCAN_BLK 256

// ---------------- device scratch (allocation-free: static globals) ----------------
__device__ float g_A[NMAX * HID];      // x @ W1a.T   [N,128]
__device__ float g_B[NMAX * HID];      // x @ W1b.T   [N,128]
__device__ float g_h1[NMAX * HID];     // h1 rows 0..N  (A[src]+B[dst])
__device__ float g_agg1[NMAX * HID];   // edge-aggregated h1
__device__ float g_wz[NMAX * FOUT];    // W2l @ r_j for j<N
__device__ float g_wa2[NMAX * FOUT];   // edge-aggregated wz
__device__ int   g_cnt[NMAX];
__device__ int   g_fill[NMAX];
__device__ int   g_rowptr[NMAX + 1];
__device__ int   g_bsum[(NMAX + SCAN_BLK - 1) / SCAN_BLK + 1];
__device__ int   g_eid[EMAX];
__device__ int   g_csrc[EMAX];
__device__ float g_cnorm[EMAX];
__device__ float g_dis[NMAX];
__device__ float g_invdeg[NMAX];
__device__ float g_part[(STATS_BLOCKS + STATS_BLOCKS_N) * 2 * HID];
__device__ float g_af[HID];
__device__ float g_cf[HID];
__device__ float g_W2l[FOUT * HID];    // Wl @ W2  [64,128]
__device__ float g_cvec[FOUT];         // Wl@b2 + bl

// ---------------- kernels ----------------

__global__ void k_zero(int Ncur) {
    int t = blockIdx.x * blockDim.x + threadIdx.x;
    if (t < Ncur) { g_cnt[t] = 0; g_fill[t] = 0; }
}

__global__ void k_count(const int* __restrict__ dst, int Ecur) {
    int e = blockIdx.x * blockDim.x + threadIdx.x;
    if (e < Ecur) atomicAdd(&g_cnt[dst[e]], 1);
}

// BN stats part E: rows i in [N, E) — pre = A[src]+B[dst]+b1.
// 8 rows per iteration: 16 independent row-gather loads in flight.
__global__ void __launch_bounds__(128) k_bnstatsE(const int* __restrict__ src,
                                                  const int* __restrict__ dst,
                                                  const float* __restrict__ b1,
                                                  int Ncur, int Ecur) {
    int f = threadIdx.x;
    float bb = b1[f];
    float s_ = 0.f, q_ = 0.f;
    int stride = gridDim.x * 8;
    for (int i = Ncur + blockIdx.x * 8; i < Ecur; i += stride) {
        int n = Ecur - i; if (n > 8) n = 8;
        int sn[8], dn[8];
#pragma unroll
        for (int k = 0; k < 8; k++) {
            int ii = (k < n) ? (i + k) : i;
            sn[k] = src[ii];
            dn[k] = dst[ii];
        }
        float vA[8], vB[8];
#pragma unroll
        for (int k = 0; k < 8; k++) {
            vA[k] = g_A[sn[k] * HID + f];
            vB[k] = g_B[dn[k] * HID + f];
        }
#pragma unroll
        for (int k = 0; k < 8; k++) {
            if (k < n) {
                float v = vA[k] + vB[k] + bb;
                s_ += v;
                q_ = fmaf(v, v, q_);
            }
        }
    }
    g_part[blockIdx.x * (2 * HID) + f]       = s_;
    g_part[blockIdx.x * (2 * HID) + HID + f] = q_;
}

// BN stats part N: rows j in [0, N) — pre = invdeg*(A[src]+B[dst]) + agg1 + b1
// Same 8-row unroll.
__global__ void __launch_bounds__(128) k_bnstatsN(const int* __restrict__ src,
                                                  const int* __restrict__ dst,
                                                  const float* __restrict__ b1,
                                                  int Ncur) {
    int f = threadIdx.x;
    float bb = b1[f];
    float s_ = 0.f, q_ = 0.f;
    int stride = gridDim.x * 8;
    for (int j = blockIdx.x * 8; j < Ncur; j += stride) {
        int n = Ncur - j; if (n > 8) n = 8;
        int sn[8], dn[8];
#pragma unroll
        for (int k = 0; k < 8; k++) {
            int jj = (k < n) ? (j + k) : j;
            sn[k] = src[jj];
            dn[k] = dst[jj];
        }
        float vA[8], vB[8], ag[8], idg[8];
#pragma unroll
        for (int k = 0; k < 8; k++) {
            int jj = (k < n) ? (j + k) : j;
            vA[k]  = g_A[sn[k] * HID + f];
            vB[k]  = g_B[dn[k] * HID + f];
            ag[k]  = g_agg1[jj * HID + f];
            idg[k] = g_invdeg[jj];
        }
#pragma unroll
        for (int k = 0; k < 8; k++) {
            if (k < n) {
                float v = idg[k] * (vA[k] + vB[k]) + ag[k] + bb;
                s_ += v;
                q_ = fmaf(v, v, q_);
            }
        }
    }
    size_t base = (size_t)(STATS_BLOCKS + blockIdx.x) * (2 * HID);
    g_part[base + f]       = s_;
    g_part[base + HID + f] = q_;
}

// scan pass 1: per-block exclusive scan + block totals; fused deg normalizers
__global__ void __launch_bounds__(SCAN_BLK) k_scan1(int Ncur) {
    __shared__ int sh[SCAN_BLK];
    int t = threadIdx.x;
    int idx = blockIdx.x * SCAN_BLK + t;
    int v = (idx < Ncur) ? g_cnt[idx] : 0;
    if (idx < Ncur) {
        float dg = (float)(v + 1);
        g_dis[idx]    = rsqrtf(dg);
        g_invdeg[idx] = 1.0f / dg;
    }
    sh[t] = v;
    __syncthreads();
#pragma unroll
    for (int off = 1; off < SCAN_BLK; off <<= 1) {
        int xv = (t >= off) ? sh[t - off] : 0;
        __syncthreads();
        sh[t] += xv;
        __syncthreads();
    }
    if (idx < Ncur) g_rowptr[idx] = sh[t] - v;
    if (t == SCAN_BLK - 1) g_bsum[blockIdx.x] = sh[t];
}

// scan pass 2: exclusive scan of block sums (nb <= SCAN_BLK)
__global__ void __launch_bounds__(SCAN_BLK) k_scan2(int nb) {
    __shared__ int sh[SCAN_BLK];
    int t = threadIdx.x;
    int v = (t < nb) ? g_bsum[t] : 0;
    sh[t] = v;
    __syncthreads();
#pragma unroll
    for (int off = 1; off < SCAN_BLK; off <<= 1) {
        int xv = (t >= off) ? sh[t - off] : 0;
        __syncthreads();
        sh[t] += xv;
        __syncthreads();
    }
    if (t < nb) g_bsum[t] = sh[t] - v;
}

// scan pass 3: apply block offsets; rowptr[N] = E
__global__ void k_scan3(int Ncur, int Ecur) {
    int idx = blockIdx.x * blockDim.x + threadIdx.x;
    if (idx < Ncur) g_rowptr[idx] += g_bsum[idx >> 8];
    if (idx == Ncur) g_rowptr[Ncur] = Ecur;
}

__global__ void k_fill(const int* __restrict__ dst, int Ecur) {
    int e = blockIdx.x * blockDim.x + threadIdx.x;
    if (e < Ecur) {
        int d = dst[e];
        int slot = g_rowptr[d] + atomicAdd(&g_fill[d], 1);
        g_eid[slot] = e;
    }
}

// sort each bucket by edge id (determinism), emit src + norm per slot.
// Buckets <= 64 sorted in a local (L1-resident) buffer.
__global__ void k_sort(const int* __restrict__ src, int Ncur) {
    int i = blockIdx.x * blockDim.x + threadIdx.x;
    if (i >= Ncur) return;
    int lo = g_rowptr[i], hi = g_rowptr[i + 1];
    int n = hi - lo;
    float di = g_dis[i];
    if (n <= 64) {
        int buf[64];
        for (int k = 0; k < n; k++) buf[k] = g_eid[lo + k];
        for (int a = 1; a < n; a++) {
            int key = buf[a];
            int b = a - 1;
            while (b >= 0 && buf[b] > key) { buf[b + 1] = buf[b]; b--; }
            buf[b + 1] = key;
        }
        for (int k = 0; k < n; k++) {
            int s = src[buf[k]];
            g_csrc[lo + k]  = s;
            g_cnorm[lo + k] = di * g_dis[s];
        }
    } else {
        for (int a = lo + 1; a < hi; a++) {
            int key = g_eid[a];
            int b = a - 1;
            while (b >= lo && g_eid[b] > key) { g_eid[b + 1] = g_eid[b]; b--; }
            g_eid[b + 1] = key;
        }
        for (int k = lo; k < hi; k++) {
            int s = src[g_eid[k]];
            g_csrc[k]  = s;
            g_cnorm[k] = di * g_dis[s];
        }
    }
}

// A = x @ W1[:, :64].T ; B = x @ W1[:, 64:].T   (16 nodes per block)
__global__ void __launch_bounds__(128) k_ab(const float* __restrict__ x,
                                            const float* __restrict__ W1, int Ncur) {
    __shared__ float xs[16][FIN];
    int j0 = blockIdx.x * 16;
    for (int idx = threadIdx.x; idx < 16 * FIN; idx += 128) {
        int j = idx >> 6, k = idx & 63;
        xs[j][k] = (j0 + j < Ncur) ? x[(j0 + j) * FIN + k] : 0.0f;
    }
    __syncthreads();
    int o = threadIdx.x;
    float accA[16], accB[16];
#pragma unroll
    for (int j = 0; j < 16; j++) { accA[j] = 0.f; accB[j] = 0.f; }
    const float* w = W1 + o * (2 * FIN);
    for (int k = 0; k < FIN; k++) {
        float wa = w[k], wb = w[FIN + k];
#pragma unroll
        for (int j = 0; j < 16; j++) {
            float xv = xs[j][k];
            accA[j] = fmaf(wa, xv, accA[j]);
            accB[j] = fmaf(wb, xv, accB[j]);
        }
    }
    for (int j = 0; j < 16; j++) {
        if (j0 + j < Ncur) {
            g_A[(j0 + j) * HID + o] = accA[j];
            g_B[(j0 + j) * HID + o] = accB[j];
        }
    }
}

// h1 rows 0..N-1: h1[j] = A[src[j]] + B[dst[j]]
__global__ void k_h1(const int* __restrict__ src, const int* __restrict__ dst, int Ncur) {
    int t = blockIdx.x * blockDim.x + threadIdx.x;
    if (t >= Ncur * HID) return;
    int j = t >> 7, f = t & 127;
    g_h1[t] = g_A[src[j] * HID + f] + g_B[dst[j] * HID + f];
}

// agg1[i] = sum over CSR bucket i of norm * h1[src]; indices staged in smem
__global__ void __launch_bounds__(128) k_agg1() {
    __shared__ int   ssrc[128];
    __shared__ float snorm[128];
    int i = blockIdx.x, f = threadIdx.x;
    int lo = g_rowptr[i], hi = g_rowptr[i + 1];
    float acc = 0.f;
    for (int base = lo; base < hi; base += 128) {
        int m = hi - base; if (m > 128) m = 128;
        if (f < m) { ssrc[f] = g_csrc[base + f]; snorm[f] = g_cnorm[base + f]; }
        __syncthreads();
        int k = 0;
        for (; k + 4 <= m; k += 4) {
            int s0 = ssrc[k], s1 = ssrc[k + 1], s2 = ssrc[k + 2], s3 = ssrc[k + 3];
            float n0 = snorm[k], n1 = snorm[k + 1], n2 = snorm[k + 2], n3 = snorm[k + 3];
            float v0 = g_h1[s0 * HID + f], v1 = g_h1[s1 * HID + f];
            float v2 = g_h1[s2 * HID + f], v3 = g_h1[s3 * HID + f];
            acc = fmaf(n0, v0, acc); acc = fmaf(n1, v1, acc);
            acc = fmaf(n2, v2, acc); acc = fmaf(n3, v3, acc);
        }
        for (; k < m; k++) acc = fmaf(snorm[k], g_h1[ssrc[k] * HID + f], acc);
        __syncthreads();
    }
    g_agg1[i * HID + f] = acc;
}

// finalize BN over both partial regions (fixed-order reduce -> deterministic)
__global__ void k_bnred(const float* __restrict__ gamma, const float* __restrict__ beta, int Ecur) {
    int f = threadIdx.x;
    float s = 0.f, q = 0.f;
    for (int b = 0; b < STATS_BLOCKS + STATS_BLOCKS_N; b++) {
        s += g_part[(size_t)b * (2 * HID) + f];
        q += g_part[(size_t)b * (2 * HID) + HID + f];
    }
    float invE = 1.0f / (float)Ecur;
    float mu  = s * invE;
    float var = q * invE - mu * mu;
    float istd = rsqrtf(var + 1e-5f);
    float a = gamma[f] * istd;
    g_af[f] = a;
    g_cf[f] = beta[f] - mu * a;
}

// W2l = Wl @ W2 ; cvec = Wl@b2 + bl
__global__ void k_w2l(const float* __restrict__ Wl, const float* __restrict__ W2,
                      const float* __restrict__ b2, const float* __restrict__ bl) {
    int t = blockIdx.x * blockDim.x + threadIdx.x;  // 8192 threads
    int o = t >> 7, f = t & 127;
    float acc = 0.f;
#pragma unroll
    for (int m = 0; m < 64; m++) acc = fmaf(Wl[o * 64 + m], W2[m * HID + f], acc);
    g_W2l[t] = acc;
    if (t < 64) {
        float cv = 0.f;
        for (int m = 0; m < 64; m++) cv = fmaf(Wl[t * 64 + m], b2[m], cv);
        g_cvec[t] = cv + bl[t];
    }
}

// wz[j] = W2l @ relu(bn(pre_j)) for j < N. 4-row batch, R4 compute structure.
__global__ void __launch_bounds__(128) k_z(const int* __restrict__ src,
                                           const int* __restrict__ dst,
                                           const float* __restrict__ b1, int Ncur) {
    int f = threadIdx.x;
    float bb = b1[f], af = g_af[f], cf = g_cf[f];
    int o = f & 63, h = f >> 6;
    float wreg[64];
#pragma unroll
    for (int k = 0; k < 64; k++) wreg[k] = g_W2l[o * HID + h * 64 + k];
    __shared__ __align__(16) float rsh[4][HID];
    __shared__ float ps[4][64];
    int stride = gridDim.x * 4;
    for (int j = blockIdx.x * 4; j < Ncur; j += stride) {
        int n = Ncur - j; if (n > 4) n = 4;
        int sn[4], dn[4];
#pragma unroll
        for (int r = 0; r < 4; r++) {
            int jj = (r < n) ? (j + r) : j;
            sn[r] = src[jj]; dn[r] = dst[jj];
        }
        float vA[4], vB[4], ag[4], idg[4];
#pragma unroll
        for (int r = 0; r < 4; r++) {
            int jj = (r < n) ? (j + r) : j;
            vA[r]  = g_A[sn[r] * HID + f];
            vB[r]  = g_B[dn[r] * HID + f];
            ag[r]  = g_agg1[jj * HID + f];
            idg[r] = g_invdeg[jj];
        }
#pragma unroll
        for (int r = 0; r < 4; r++) {
            float v = idg[r] * (vA[r] + vB[r]) + ag[r] + bb;
            rsh[r][f] = fmaxf(fmaf(af, v, cf), 0.f);
        }
        __syncthreads();
        float part[4];
#pragma unroll
        for (int r = 0; r < 4; r++) {
            const float4* r4 = (const float4*)(rsh[r] + h * 64);
            float a0 = 0.f, a1 = 0.f, a2 = 0.f, a3 = 0.f;
#pragma unroll
            for (int k = 0; k < 16; k++) {
                float4 rv = r4[k];
                a0 = fmaf(wreg[4 * k + 0], rv.x, a0);
                a1 = fmaf(wreg[4 * k + 1], rv.y, a1);
                a2 = fmaf(wreg[4 * k + 2], rv.z, a2);
                a3 = fmaf(wreg[4 * k + 3], rv.w, a3);
            }
            part[r] = (a0 + a1) + (a2 + a3);
            if (h) ps[r][o] = part[r];
        }
        __syncthreads();
        if (!h) {
#pragma unroll
            for (int r = 0; r < 4; r++)
                if (r < n) g_wz[(j + r) * FOUT + o] = part[r] + ps[r][o];
        }
        __syncthreads();
    }
}

// wa2[i] = sum over bucket i of norm * wz[src]; indices staged in smem
__global__ void __launch_bounds__(64) k_agg2() {
    __shared__ int   ssrc[64];
    __shared__ float snorm[64];
    int i = blockIdx.x, f = threadIdx.x;
    int lo = g_rowptr[i], hi = g_rowptr[i + 1];
    float acc = 0.f;
    for (int base = lo; base < hi; base += 64) {
        int m = hi - base; if (m > 64) m = 64;
        if (f < m) { ssrc[f] = g_csrc[base + f]; snorm[f] = g_cnorm[base + f]; }
        __syncthreads();
        int k = 0;
        for (; k + 4 <= m; k += 4) {
            int s0 = ssrc[k], s1 = ssrc[k + 1], s2 = ssrc[k + 2], s3 = ssrc[k + 3];
            float n0 = snorm[k], n1 = snorm[k + 1], n2 = snorm[k + 2], n3 = snorm[k + 3];
            float v0 = g_wz[s0 * FOUT + f], v1 = g_wz[s1 * FOUT + f];
            float v2 = g_wz[s2 * FOUT + f], v3 = g_wz[s3 * FOUT + f];
            acc = fmaf(n0, v0, acc); acc = fmaf(n1, v1, acc);
            acc = fmaf(n2, v2, acc); acc = fmaf(n3, v3, acc);
        }
        for (; k < m; k++) acc = fmaf(snorm[k], g_wz[ssrc[k] * FOUT + f], acc);
        __syncthreads();
    }
    g_wa2[i * FOUT + f] = acc;
}

// rows i < N: y = invdeg*wz + wa2 + cvec  (pure elementwise)
__global__ void k_small(const float* __restrict__ cutp, float* __restrict__ outp,
                        float* __restrict__ outr, int Ncur) {
    int t = blockIdx.x * blockDim.x + threadIdx.x;
    if (t >= Ncur * FOUT) return;
    int i = t >> 6, o = t & 63;
    float y = g_invdeg[i] * g_wz[t] + g_wa2[t] + g_cvec[o];
    float p = 1.0f / (1.0f + expf(-y));
    outp[t] = p;
    outr[t] = (p < *cutp) ? 0.0f : 1.0f;
}

// rows i in [N, E): R4 compute structure, batched 4 rows/iter for gather MLP
// and barrier amortization (3 syncs per 4 rows instead of 12).
__global__ void __launch_bounds__(128) k_final(const int* __restrict__ src,
                                               const int* __restrict__ dst,
                                               const float* __restrict__ b1,
                                               const float* __restrict__ cutp,
                                               float* __restrict__ outp,
                                               float* __restrict__ outr,
                                               int Ncur, int Ecur) {
    int f = threadIdx.x;
    float bb = b1[f], af = g_af[f], cf = g_cf[f];
    int o = f & 63, h = f >> 6;
    float wreg[64];
#pragma unroll
    for (int k = 0; k < 64; k++) wreg[k] = g_W2l[o * HID + h * 64 + k];
    float cv  = g_cvec[o];
    float cut = *cutp;
    __shared__ __align__(16) float rsh[4][HID];
    __shared__ float ps[4][64];

    int stride = gridDim.x * 4;
    for (int i = Ncur + blockIdx.x * 4; i < Ecur; i += stride) {
        int n = Ecur - i; if (n > 4) n = 4;
        int sn[4], dn[4];
#pragma unroll
        for (int r = 0; r < 4; r++) {
            int ii = (r < n) ? (i + r) : i;
            sn[r] = src[ii]; dn[r] = dst[ii];
        }
        float vA[4], vB[4];
#pragma unroll
        for (int r = 0; r < 4; r++) {
            vA[r] = g_A[sn[r] * HID + f];
            vB[r] = g_B[dn[r] * HID + f];
        }
#pragma unroll
        for (int r = 0; r < 4; r++)
            rsh[r][f] = fmaxf(fmaf(af, vA[r] + vB[r] + bb, cf), 0.f);
        __syncthreads();

        float part[4];
#pragma unroll
        for (int r = 0; r < 4; r++) {
            const float4* r4 = (const float4*)(rsh[r] + h * 64);
            float a0 = 0.f, a1 = 0.f, a2 = 0.f, a3 = 0.f;
#pragma unroll
            for (int k = 0; k < 16; k++) {
                float4 rv = r4[k];
                a0 = fmaf(wreg[4 * k + 0], rv.x, a0);
                a1 = fmaf(wreg[4 * k + 1], rv.y, a1);
                a2 = fmaf(wreg[4 * k + 2], rv.z, a2);
                a3 = fmaf(wreg[4 * k + 3], rv.w, a3);
            }
            part[r] = (a0 + a1) + (a2 + a3);
            if (h) ps[r][o] = part[r];
        }
        __syncthreads();
        if (!h) {
#pragma unroll
            for (int r = 0; r < 4; r++) {
                if (r < n) {
                    float y = (part[r] + ps[r][o]) + cv;
                    float p = 1.0f / (1.0f + expf(-y));
                    size_t off = (size_t)(i + r) * FOUT + o;
                    outp[off] = p;
                    outr[off] = (p < cut) ? 0.0f : 1.0f;
                }
            }
        }
        __syncthreads();
    }
}

// ---------------- launch ----------------
extern "C" void kernel_launch(void* const* d_in, const int* in_sizes, int n_in,
                              void* d_out, int out_size) {
    const float* x     = (const float*)d_in[0];
    const int*   edge  = (const int*)d_in[1];
    const float* W1    = (const float*)d_in[2];
    const float* b1    = (const float*)d_in[3];
    const float* gamma = (const float*)d_in[4];
    const float* beta  = (const float*)d_in[5];
    const float* W2    = (const float*)d_in[6];
    const float* b2    = (const float*)d_in[7];
    const float* Wl    = (const float*)d_in[8];
    const float* bl    = (const float*)d_in[9];
    const float* cut   = (const float*)d_in[10];

    int Ncur = in_sizes[0] / FIN;
    int Ecur = in_sizes[1] / 2;
    if (Ncur > NMAX || Ecur > EMAX || Ncur <= 0 || Ecur <= 0) return;

    const int* src = edge;
    const int* dst = edge + Ecur;
    float* outp = (float*)d_out;
    float* outr = outp + (size_t)out_size / 2;

    int nb = (Ncur + SCAN_BLK - 1) / SCAN_BLK;

    // k_bnstatsE stays at launch index 3 (ncu capture window): verify 8-row
    // unroll prediction 118us -> ~75us.
    k_ab       <<<(Ncur + 15) / 16, 128>>>(x, W1, Ncur);           // 0
    k_zero     <<<(Ncur + 255) / 256, 256>>>(Ncur);                // 1
    k_count    <<<(Ecur + 255) / 256, 256>>>(dst, Ecur);           // 2
    k_bnstatsE <<<STATS_BLOCKS, 128>>>(src, dst, b1, Ncur, Ecur);  // 3 (profiled)
    k_scan1    <<<nb, SCAN_BLK>>>(Ncur);                           // 4
    k_scan2    <<<1, SCAN_BLK>>>(nb);                              // 5
    k_scan3    <<<(Ncur + 256) / 256, 256>>>(Ncur, Ecur);          // 6
    k_fill     <<<(Ecur + 255) / 256, 256>>>(dst, Ecur);           // 7
    k_sort     <<<(Ncur + 127) / 128, 128>>>(src, Ncur);           // 8
    k_h1       <<<(Ncur * HID + 255) / 256, 256>>>(src, dst, Ncur);// 9
    k_agg1     <<<Ncur, 128>>>();                                  // 10
    k_bnstatsN <<<STATS_BLOCKS_N, 128>>>(src, dst, b1, Ncur);      // 11
    k_bnred    <<<1, 128>>>(gamma, beta, Ecur);                    // 12
    k_w2l      <<<64, 128>>>(Wl, W2, b2, bl);                      // 13
    {
        int groups = (Ncur + 3) / 4;
        int g = groups < 2048 ? groups : 2048;
        k_z<<<g, 128>>>(src, dst, b1, Ncur);                       // 14
    }
    k_agg2     <<<Ncur, 64>>>();                                   // 15
    k_small    <<<(Ncur * FOUT + 255) / 256, 256>>>(cut, outp, outr, Ncur); // 16
    {
        int rows = Ecur - Ncur;
        if (rows > 0) {
            int groups = (rows + 3) / 4;
            int g = groups < 4096 ? groups : 4096;
            k_final<<<g, 128>>>(src, dst, b1, cut, outp, outr, Ncur, Ecur); // 17
        }
    }
}

// round 10
// speedup vs baseline: 1.8050x; 1.0774x over previous
#include <cuda_runtime.h>
#include <math.h>

// Problem constants (fixed shapes from reference setup_inputs)
#define NMAX 40000
#define EMAX 640000
#define HID  128
#define FIN  64
#define FOUT 64
#define STATS_BLOCKS 1024
#define STATS_BLOCKS_N 256
#define SCAN_BLK 256

// ---------------- device scratch (allocation-free: static globals) ----------------
__device__ float g_A[NMAX * HID];      // x @ W1a.T   [N,128]
__device__ float g_B[NMAX * HID];      // x @ W1b.T   [N,128]
__device__ float g_h1[NMAX * HID];     // h1 rows 0..N  (A[src]+B[dst])
__device__ float g_agg1[NMAX * HID];   // edge-aggregated h1
__device__ float g_wz[NMAX * FOUT];    // W2l @ r_j for j<N
__device__ float g_wa2[NMAX * FOUT];   // edge-aggregated wz
__device__ int   g_cnt[NMAX];
__device__ int   g_fill[NMAX];
__device__ int   g_rowptr[NMAX + 1];
__device__ int   g_bsum[(NMAX + SCAN_BLK - 1) / SCAN_BLK + 1];
__device__ int   g_eid[EMAX];
__device__ int   g_csrc[EMAX];
__device__ float g_cnorm[EMAX];
__device__ float g_dis[NMAX];
__device__ float g_invdeg[NMAX];
__device__ float g_part[(STATS_BLOCKS + STATS_BLOCKS_N) * 2 * HID];
__device__ float g_af[HID];
__device__ float g_cf[HID];
__device__ float g_W2l[FOUT * HID];    // Wl @ W2  [64,128]
__device__ float g_cvec[FOUT];         // Wl@b2 + bl

// ---------------- f32x2 helpers ----------------
__device__ __forceinline__ unsigned long long fma2(unsigned long long a,
                                                   unsigned long long b,
                                                   unsigned long long c) {
    unsigned long long d;
    asm("fma.rn.f32x2 %0, %1, %2, %3;" : "=l"(d) : "l"(a), "l"(b), "l"(c));
    return d;
}
__device__ __forceinline__ unsigned long long add2(unsigned long long a,
                                                   unsigned long long b) {
    unsigned long long d;
    asm("add.rn.f32x2 %0, %1, %2;" : "=l"(d) : "l"(a), "l"(b));
    return d;
}
__device__ __forceinline__ unsigned long long packf2(float lo, float hi) {
    return ((unsigned long long)__float_as_uint(hi) << 32) | __float_as_uint(lo);
}
__device__ __forceinline__ float f2lo(unsigned long long a) {
    return __uint_as_float((unsigned int)a);
}
__device__ __forceinline__ float f2hi(unsigned long long a) {
    return __uint_as_float((unsigned int)(a >> 32));
}

// ---------------- kernels ----------------

__global__ void k_zero(int Ncur) {
    int t = blockIdx.x * blockDim.x + threadIdx.x;
    if (t < Ncur) { g_cnt[t] = 0; g_fill[t] = 0; }
}

__global__ void k_count(const int* __restrict__ dst, int Ecur) {
    int e = blockIdx.x * blockDim.x + threadIdx.x;
    if (e < Ecur) atomicAdd(&g_cnt[dst[e]], 1);
}

// BN stats part E: rows i in [N, E) — pre = A[src]+B[dst]+b1.
// 8 rows per iteration; predication-free main loop + scalar tail.
__global__ void __launch_bounds__(128) k_bnstatsE(const int* __restrict__ src,
                                                  const int* __restrict__ dst,
                                                  const float* __restrict__ b1,
                                                  int Ncur, int Ecur) {
    int f = threadIdx.x;
    float bb = b1[f];
    float s_ = 0.f, q_ = 0.f;
    int stride = gridDim.x * 8;
    int i = Ncur + blockIdx.x * 8;
    for (; i + 8 <= Ecur; i += stride) {
        int sn[8], dn[8];
#pragma unroll
        for (int k = 0; k < 8; k++) { sn[k] = src[i + k]; dn[k] = dst[i + k]; }
        float vA[8], vB[8];
#pragma unroll
        for (int k = 0; k < 8; k++) {
            vA[k] = g_A[sn[k] * HID + f];
            vB[k] = g_B[dn[k] * HID + f];
        }
#pragma unroll
        for (int k = 0; k < 8; k++) {
            float v = vA[k] + vB[k] + bb;
            s_ += v;
            q_ = fmaf(v, v, q_);
        }
    }
    for (; i < Ecur; i++) {
        float v = g_A[src[i] * HID + f] + g_B[dst[i] * HID + f] + bb;
        s_ += v;
        q_ = fmaf(v, v, q_);
    }
    g_part[blockIdx.x * (2 * HID) + f]       = s_;
    g_part[blockIdx.x * (2 * HID) + HID + f] = q_;
}

// BN stats part N: rows j in [0, N) — pre = invdeg*(A[src]+B[dst]) + agg1 + b1
__global__ void __launch_bounds__(128) k_bnstatsN(const int* __restrict__ src,
                                                  const int* __restrict__ dst,
                                                  const float* __restrict__ b1,
                                                  int Ncur) {
    int f = threadIdx.x;
    float bb = b1[f];
    float s_ = 0.f, q_ = 0.f;
    int stride = gridDim.x * 8;
    int j = blockIdx.x * 8;
    for (; j + 8 <= Ncur; j += stride) {
        int sn[8], dn[8];
#pragma unroll
        for (int k = 0; k < 8; k++) { sn[k] = src[j + k]; dn[k] = dst[j + k]; }
        float vA[8], vB[8], ag[8], idg[8];
#pragma unroll
        for (int k = 0; k < 8; k++) {
            vA[k]  = g_A[sn[k] * HID + f];
            vB[k]  = g_B[dn[k] * HID + f];
            ag[k]  = g_agg1[(j + k) * HID + f];
            idg[k] = g_invdeg[j + k];
        }
#pragma unroll
        for (int k = 0; k < 8; k++) {
            float v = idg[k] * (vA[k] + vB[k]) + ag[k] + bb;
            s_ += v;
            q_ = fmaf(v, v, q_);
        }
    }
    for (; j < Ncur; j++) {
        float v = g_invdeg[j] * (g_A[src[j] * HID + f] + g_B[dst[j] * HID + f])
                + g_agg1[j * HID + f] + bb;
        s_ += v;
        q_ = fmaf(v, v, q_);
    }
    size_t base = (size_t)(STATS_BLOCKS + blockIdx.x) * (2 * HID);
    g_part[base + f]       = s_;
    g_part[base + HID + f] = q_;
}

// scan pass 1: per-block exclusive scan + block totals; fused deg normalizers
__global__ void __launch_bounds__(SCAN_BLK) k_scan1(int Ncur) {
    __shared__ int sh[SCAN_BLK];
    int t = threadIdx.x;
    int idx = blockIdx.x * SCAN_BLK + t;
    int v = (idx < Ncur) ? g_cnt[idx] : 0;
    if (idx < Ncur) {
        float dg = (float)(v + 1);
        g_dis[idx]    = rsqrtf(dg);
        g_invdeg[idx] = 1.0f / dg;
    }
    sh[t] = v;
    __syncthreads();
#pragma unroll
    for (int off = 1; off < SCAN_BLK; off <<= 1) {
        int xv = (t >= off) ? sh[t - off] : 0;
        __syncthreads();
        sh[t] += xv;
        __syncthreads();
    }
    if (idx < Ncur) g_rowptr[idx] = sh[t] - v;
    if (t == SCAN_BLK - 1) g_bsum[blockIdx.x] = sh[t];
}

// scan pass 2: exclusive scan of block sums (nb <= SCAN_BLK)
__global__ void __launch_bounds__(SCAN_BLK) k_scan2(int nb) {
    __shared__ int sh[SCAN_BLK];
    int t = threadIdx.x;
    int v = (t < nb) ? g_bsum[t] : 0;
    sh[t] = v;
    __syncthreads();
#pragma unroll
    for (int off = 1; off < SCAN_BLK; off <<= 1) {
        int xv = (t >= off) ? sh[t - off] : 0;
        __syncthreads();
        sh[t] += xv;
        __syncthreads();
    }
    if (t < nb) g_bsum[t] = sh[t] - v;
}

// scan pass 3: apply block offsets; rowptr[N] = E
__global__ void k_scan3(int Ncur, int Ecur) {
    int idx = blockIdx.x * blockDim.x + threadIdx.x;
    if (idx < Ncur) g_rowptr[idx] += g_bsum[idx >> 8];
    if (idx == Ncur) g_rowptr[Ncur] = Ecur;
}

__global__ void k_fill(const int* __restrict__ dst, int Ecur) {
    int e = blockIdx.x * blockDim.x + threadIdx.x;
    if (e < Ecur) {
        int d = dst[e];
        int slot = g_rowptr[d] + atomicAdd(&g_fill[d], 1);
        g_eid[slot] = e;
    }
}

// sort each bucket by edge id (determinism), emit src + norm per slot.
__global__ void k_sort(const int* __restrict__ src, int Ncur) {
    int i = blockIdx.x * blockDim.x + threadIdx.x;
    if (i >= Ncur) return;
    int lo = g_rowptr[i], hi = g_rowptr[i + 1];
    int n = hi - lo;
    float di = g_dis[i];
    if (n <= 64) {
        int buf[64];
        for (int k = 0; k < n; k++) buf[k] = g_eid[lo + k];
        for (int a = 1; a < n; a++) {
            int key = buf[a];
            int b = a - 1;
            while (b >= 0 && buf[b] > key) { buf[b + 1] = buf[b]; b--; }
            buf[b + 1] = key;
        }
        for (int k = 0; k < n; k++) {
            int s = src[buf[k]];
            g_csrc[lo + k]  = s;
            g_cnorm[lo + k] = di * g_dis[s];
        }
    } else {
        for (int a = lo + 1; a < hi; a++) {
            int key = g_eid[a];
            int b = a - 1;
            while (b >= lo && g_eid[b] > key) { g_eid[b + 1] = g_eid[b]; b--; }
            g_eid[b + 1] = key;
        }
        for (int k = lo; k < hi; k++) {
            int s = src[g_eid[k]];
            g_csrc[k]  = s;
            g_cnorm[k] = di * g_dis[s];
        }
    }
}

// A = x @ W1[:, :64].T ; B = x @ W1[:, 64:].T   (16 nodes per block)
__global__ void __launch_bounds__(128) k_ab(const float* __restrict__ x,
                                            const float* __restrict__ W1, int Ncur) {
    __shared__ float xs[16][FIN];
    int j0 = blockIdx.x * 16;
    for (int idx = threadIdx.x; idx < 16 * FIN; idx += 128) {
        int j = idx >> 6, k = idx & 63;
        xs[j][k] = (j0 + j < Ncur) ? x[(j0 + j) * FIN + k] : 0.0f;
    }
    __syncthreads();
    int o = threadIdx.x;
    float accA[16], accB[16];
#pragma unroll
    for (int j = 0; j < 16; j++) { accA[j] = 0.f; accB[j] = 0.f; }
    const float* w = W1 + o * (2 * FIN);
    for (int k = 0; k < FIN; k++) {
        float wa = w[k], wb = w[FIN + k];
#pragma unroll
        for (int j = 0; j < 16; j++) {
            float xv = xs[j][k];
            accA[j] = fmaf(wa, xv, accA[j]);
            accB[j] = fmaf(wb, xv, accB[j]);
        }
    }
    for (int j = 0; j < 16; j++) {
        if (j0 + j < Ncur) {
            g_A[(j0 + j) * HID + o] = accA[j];
            g_B[(j0 + j) * HID + o] = accB[j];
        }
    }
}

// h1 rows 0..N-1: h1[j] = A[src[j]] + B[dst[j]]
__global__ void k_h1(const int* __restrict__ src, const int* __restrict__ dst, int Ncur) {
    int t = blockIdx.x * blockDim.x + threadIdx.x;
    if (t >= Ncur * HID) return;
    int j = t >> 7, f = t & 127;
    g_h1[t] = g_A[src[j] * HID + f] + g_B[dst[j] * HID + f];
}

// agg1[i] = sum over CSR bucket i of norm * h1[src]; indices staged in smem
__global__ void __launch_bounds__(128) k_agg1() {
    __shared__ int   ssrc[128];
    __shared__ float snorm[128];
    int i = blockIdx.x, f = threadIdx.x;
    int lo = g_rowptr[i], hi = g_rowptr[i + 1];
    float acc = 0.f;
    for (int base = lo; base < hi; base += 128) {
        int m = hi - base; if (m > 128) m = 128;
        if (f < m) { ssrc[f] = g_csrc[base + f]; snorm[f] = g_cnorm[base + f]; }
        __syncthreads();
        int k = 0;
        for (; k + 4 <= m; k += 4) {
            int s0 = ssrc[k], s1 = ssrc[k + 1], s2 = ssrc[k + 2], s3 = ssrc[k + 3];
            float n0 = snorm[k], n1 = snorm[k + 1], n2 = snorm[k + 2], n3 = snorm[k + 3];
            float v0 = g_h1[s0 * HID + f], v1 = g_h1[s1 * HID + f];
            float v2 = g_h1[s2 * HID + f], v3 = g_h1[s3 * HID + f];
            acc = fmaf(n0, v0, acc); acc = fmaf(n1, v1, acc);
            acc = fmaf(n2, v2, acc); acc = fmaf(n3, v3, acc);
        }
        for (; k < m; k++) acc = fmaf(snorm[k], g_h1[ssrc[k] * HID + f], acc);
        __syncthreads();
    }
    g_agg1[i * HID + f] = acc;
}

// finalize BN over both partial regions (fixed-order reduce -> deterministic)
__global__ void k_bnred(const float* __restrict__ gamma, const float* __restrict__ beta, int Ecur) {
    int f = threadIdx.x;
    float s = 0.f, q = 0.f;
    for (int b = 0; b < STATS_BLOCKS + STATS_BLOCKS_N; b++) {
        s += g_part[(size_t)b * (2 * HID) + f];
        q += g_part[(size_t)b * (2 * HID) + HID + f];
    }
    float invE = 1.0f / (float)Ecur;
    float mu  = s * invE;
    float var = q * invE - mu * mu;
    float istd = rsqrtf(var + 1e-5f);
    float a = gamma[f] * istd;
    g_af[f] = a;
    g_cf[f] = beta[f] - mu * a;
}

// W2l = Wl @ W2 ; cvec = Wl@b2 + bl
__global__ void k_w2l(const float* __restrict__ Wl, const float* __restrict__ W2,
                      const float* __restrict__ b2, const float* __restrict__ bl) {
    int t = blockIdx.x * blockDim.x + threadIdx.x;  // 8192 threads
    int o = t >> 7, f = t & 127;
    float acc = 0.f;
#pragma unroll
    for (int m = 0; m < 64; m++) acc = fmaf(Wl[o * 64 + m], W2[m * HID + f], acc);
    g_W2l[t] = acc;
    if (t < 64) {
        float cv = 0.f;
        for (int m = 0; m < 64; m++) cv = fmaf(Wl[t * 64 + m], b2[m], cv);
        g_cvec[t] = cv + bl[t];
    }
}

// wz[j] = W2l @ relu(bn(pre_j)) for j < N. 4-row batch, f32x2 matvec.
__global__ void __launch_bounds__(128) k_z(const int* __restrict__ src,
                                           const int* __restrict__ dst,
                                           const float* __restrict__ b1, int Ncur) {
    int f = threadIdx.x;
    float bb = b1[f], af = g_af[f], cf = g_cf[f];
    int o = f & 63, h = f >> 6;
    unsigned long long wp[32];
    {
        const float2* wrow = (const float2*)(g_W2l + o * HID + h * 64);
#pragma unroll
        for (int j = 0; j < 32; j++) { float2 w = wrow[j]; wp[j] = packf2(w.x, w.y); }
    }
    __shared__ __align__(16) float rsh[4][HID];
    __shared__ float ps[4][64];
    int stride = gridDim.x * 4;
    for (int j = blockIdx.x * 4; j < Ncur; j += stride) {
        int n = Ncur - j; if (n > 4) n = 4;
        int sn[4], dn[4];
#pragma unroll
        for (int r = 0; r < 4; r++) {
            int jj = (r < n) ? (j + r) : j;
            sn[r] = src[jj]; dn[r] = dst[jj];
        }
        float vA[4], vB[4], ag[4], idg[4];
#pragma unroll
        for (int r = 0; r < 4; r++) {
            int jj = (r < n) ? (j + r) : j;
            vA[r]  = g_A[sn[r] * HID + f];
            vB[r]  = g_B[dn[r] * HID + f];
            ag[r]  = g_agg1[jj * HID + f];
            idg[r] = g_invdeg[jj];
        }
#pragma unroll
        for (int r = 0; r < 4; r++) {
            float v = idg[r] * (vA[r] + vB[r]) + ag[r] + bb;
            rsh[r][f] = fmaxf(fmaf(af, v, cf), 0.f);
        }
        __syncthreads();
        float part[4];
#pragma unroll
        for (int r = 0; r < 4; r++) {
            const ulonglong2* r2 = (const ulonglong2*)(rsh[r] + h * 64);
            unsigned long long a0 = 0ull, a1 = 0ull, a2 = 0ull, a3 = 0ull;
#pragma unroll
            for (int k = 0; k < 8; k++) {
                ulonglong2 u0 = r2[2 * k];
                ulonglong2 u1 = r2[2 * k + 1];
                a0 = fma2(wp[4 * k + 0], u0.x, a0);
                a1 = fma2(wp[4 * k + 1], u0.y, a1);
                a2 = fma2(wp[4 * k + 2], u1.x, a2);
                a3 = fma2(wp[4 * k + 3], u1.y, a3);
            }
            a0 = add2(a0, a1); a2 = add2(a2, a3); a0 = add2(a0, a2);
            part[r] = f2lo(a0) + f2hi(a0);
            if (h) ps[r][o] = part[r];
        }
        __syncthreads();
        if (!h) {
#pragma unroll
            for (int r = 0; r < 4; r++)
                if (r < n) g_wz[(j + r) * FOUT + o] = part[r] + ps[r][o];
        }
        __syncthreads();
    }
}

// wa2[i] = sum over bucket i of norm * wz[src]; indices staged in smem
__global__ void __launch_bounds__(64) k_agg2() {
    __shared__ int   ssrc[64];
    __shared__ float snorm[64];
    int i = blockIdx.x, f = threadIdx.x;
    int lo = g_rowptr[i], hi = g_rowptr[i + 1];
    float acc = 0.f;
    for (int base = lo; base < hi; base += 64) {
        int m = hi - base; if (m > 64) m = 64;
        if (f < m) { ssrc[f] = g_csrc[base + f]; snorm[f] = g_cnorm[base + f]; }
        __syncthreads();
        int k = 0;
        for (; k + 4 <= m; k += 4) {
            int s0 = ssrc[k], s1 = ssrc[k + 1], s2 = ssrc[k + 2], s3 = ssrc[k + 3];
            float n0 = snorm[k], n1 = snorm[k + 1], n2 = snorm[k + 2], n3 = snorm[k + 3];
            float v0 = g_wz[s0 * FOUT + f], v1 = g_wz[s1 * FOUT + f];
            float v2 = g_wz[s2 * FOUT + f], v3 = g_wz[s3 * FOUT + f];
            acc = fmaf(n0, v0, acc); acc = fmaf(n1, v1, acc);
            acc = fmaf(n2, v2, acc); acc = fmaf(n3, v3, acc);
        }
        for (; k < m; k++) acc = fmaf(snorm[k], g_wz[ssrc[k] * FOUT + f], acc);
        __syncthreads();
    }
    g_wa2[i * FOUT + f] = acc;
}

// rows i < N: y = invdeg*wz + wa2 + cvec  (pure elementwise)
__global__ void k_small(const float* __restrict__ cutp, float* __restrict__ outp,
                        float* __restrict__ outr, int Ncur) {
    int t = blockIdx.x * blockDim.x + threadIdx.x;
    if (t >= Ncur * FOUT) return;
    int i = t >> 6, o = t & 63;
    float y = g_invdeg[i] * g_wz[t] + g_wa2[t] + g_cvec[o];
    float p = 1.0f / (1.0f + expf(-y));
    outp[t] = p;
    outr[t] = (p < *cutp) ? 0.0f : 1.0f;
}

// rows i in [N, E): 4-row batch, f32x2 matvec (halved FFMA issue), R9 structure.
__global__ void __launch_bounds__(128) k_final(const int* __restrict__ src,
                                               const int* __restrict__ dst,
                                               const float* __restrict__ b1,
                                               const float* __restrict__ cutp,
                                               float* __restrict__ outp,
                                               float* __restrict__ outr,
                                               int Ncur, int Ecur) {
    int f = threadIdx.x;
    float bb = b1[f], af = g_af[f], cf = g_cf[f];
    int o = f & 63, h = f >> 6;
    unsigned long long wp[32];
    {
        const float2* wrow = (const float2*)(g_W2l + o * HID + h * 64);
#pragma unroll
        for (int j = 0; j < 32; j++) { float2 w = wrow[j]; wp[j] = packf2(w.x, w.y); }
    }
    float cv  = g_cvec[o];
    float cut = *cutp;
    __shared__ __align__(16) float rsh[4][HID];
    __shared__ float ps[4][64];

    int stride = gridDim.x * 4;
    for (int i = Ncur + blockIdx.x * 4; i < Ecur; i += stride) {
        int n = Ecur - i; if (n > 4) n = 4;
        int sn[4], dn[4];
#pragma unroll
        for (int r = 0; r < 4; r++) {
            int ii = (r < n) ? (i + r) : i;
            sn[r] = src[ii]; dn[r] = dst[ii];
        }
        float vA[4], vB[4];
#pragma unroll
        for (int r = 0; r < 4; r++) {
            vA[r] = g_A[sn[r] * HID + f];
            vB[r] = g_B[dn[r] * HID + f];
        }
#pragma unroll
        for (int r = 0; r < 4; r++)
            rsh[r][f] = fmaxf(fmaf(af, vA[r] + vB[r] + bb, cf), 0.f);
        __syncthreads();

        float part[4];
#pragma unroll
        for (int r = 0; r < 4; r++) {
            const ulonglong2* r2 = (const ulonglong2*)(rsh[r] + h * 64);
            unsigned long long a0 = 0ull, a1 = 0ull, a2 = 0ull, a3 = 0ull;
#pragma unroll
            for (int k = 0; k < 8; k++) {
                ulonglong2 u0 = r2[2 * k];
                ulonglong2 u1 = r2[2 * k + 1];
                a0 = fma2(wp[4 * k + 0], u0.x, a0);
                a1 = fma2(wp[4 * k + 1], u0.y, a1);
                a2 = fma2(wp[4 * k + 2], u1.x, a2);
                a3 = fma2(wp[4 * k + 3], u1.y, a3);
            }
            a0 = add2(a0, a1); a2 = add2(a2, a3); a0 = add2(a0, a2);
            part[r] = f2lo(a0) + f2hi(a0);
            if (h) ps[r][o] = part[r];
        }
        __syncthreads();
        if (!h) {
#pragma unroll
            for (int r = 0; r < 4; r++) {
                if (r < n) {
                    float y = (part[r] + ps[r][o]) + cv;
                    float p = 1.0f / (1.0f + expf(-y));
                    size_t off = (size_t)(i + r) * FOUT + o;
                    outp[off] = p;
                    outr[off] = (p < cut) ? 0.0f : 1.0f;
                }
            }
        }
        __syncthreads();
    }
}

// ---------------- launch ----------------
extern "C" void kernel_launch(void* const* d_in, const int* in_sizes, int n_in,
                              void* d_out, int out_size) {
    const float* x     = (const float*)d_in[0];
    const int*   edge  = (const int*)d_in[1];
    const float* W1    = (const float*)d_in[2];
    const float* b1    = (const float*)d_in[3];
    const float* gamma = (const float*)d_in[4];
    const float* beta  = (const float*)d_in[5];
    const float* W2    = (const float*)d_in[6];
    const float* b2    = (const float*)d_in[7];
    const float* Wl    = (const float*)d_in[8];
    const float* bl    = (const float*)d_in[9];
    const float* cut   = (const float*)d_in[10];

    int Ncur = in_sizes[0] / FIN;
    int Ecur = in_sizes[1] / 2;
    if (Ncur > NMAX || Ecur > EMAX || Ncur <= 0 || Ecur <= 0) return;

    const int* src = edge;
    const int* dst = edge + Ecur;
    float* outp = (float*)d_out;
    float* outr = outp + (size_t)out_size / 2;

    int nb = (Ncur + SCAN_BLK - 1) / SCAN_BLK;

    // k_bnstatsE stays at launch index 3 (ncu capture window): verify
    // predication-free main loop prediction 95us -> ~75us, alu% < fma%.
    k_ab       <<<(Ncur + 15) / 16, 128>>>(x, W1, Ncur);           // 0
    k_zero     <<<(Ncur + 255) / 256, 256>>>(Ncur);                // 1
    k_count    <<<(Ecur + 255) / 256, 256>>>(dst, Ecur);           // 2
    k_bnstatsE <<<STATS_BLOCKS, 128>>>(src, dst, b1, Ncur, Ecur);  // 3 (profiled)
    k_scan1    <<<nb, SCAN_BLK>>>(Ncur);                           // 4
    k_scan2    <<<1, SCAN_BLK>>>(nb);                              // 5
    k_scan3    <<<(Ncur + 256) / 256, 256>>>(Ncur, Ecur);          // 6
    k_fill     <<<(Ecur + 255) / 256, 256>>>(dst, Ecur);           // 7
    k_sort     <<<(Ncur + 127) / 128, 128>>>(src, Ncur);           // 8
    k_h1       <<<(Ncur * HID + 255) / 256, 256>>>(src, dst, Ncur);// 9
    k_agg1     <<<Ncur, 128>>>();                                  // 10
    k_bnstatsN <<<STATS_BLOCKS_N, 128>>>(src, dst, b1, Ncur);      // 11
    k_bnred    <<<1, 128>>>(gamma, beta, Ecur);                    // 12
    k_w2l      <<<64, 128>>>(Wl, W2, b2, bl);                      // 13
    {
        int groups = (Ncur + 3) / 4;
        int g = groups < 2048 ? groups : 2048;
        k_z<<<g, 128>>>(src, dst, b1, Ncur);                       // 14
    }
    k_agg2     <<<Ncur, 64>>>();                                   // 15
    k_small    <<<(Ncur * FOUT + 255) / 256, 256>>>(cut, outp, outr, Ncur); // 16
    {
        int rows = Ecur - Ncur;
        if (rows > 0) {
            int groups = (rows + 3) / 4;
            int g = groups < 4096 ? groups : 4096;
            k_final<<<g, 128>>>(src, dst, b1, cut, outp, outr, Ncur, Ecur); // 17
        }
    }
}